// round 3
// baseline (speedup 1.0000x reference)
#include <cuda_runtime.h>
#include <math.h>

#define MM 2048
#define BB 64
#define TT 4
#define DD 128
#define VV 50000

#define OG_GRID 143
#define OG_CHUNK 352   // 11 tiles of 32 rows; 143*352 = 50336 >= 50000
#define PG_GRID 391    // ceil(50000/128)

// Scratch (device globals: allocation-free rule). 16B-aligned for vector access.
__device__ __align__(16) float g_w[BB * VV];                 // scatter weights  [b][v]
__device__ __align__(16) float g_p[BB * VV];                 // p = C[h] @ u^T   [b][v]
__device__ __align__(16) float g_opart[OG_GRID * BB * DD];   // per-block GEMM partials
__device__ int g_is64;                                       // story dtype flag

typedef unsigned long long ull;

__device__ __forceinline__ ull pack2(float x, float y) {
    ull r;
    asm("mov.b64 %0, {%1,%2};" : "=l"(r) : "f"(x), "f"(y));
    return r;
}
__device__ __forceinline__ ull fma2(ull a, ull b, ull c) {
    ull d;
    asm("fma.rn.f32x2 %0, %1, %2, %3;" : "=l"(d) : "l"(a), "l"(b), "l"(c));
    return d;
}
__device__ __forceinline__ float2 unpack2(ull a) {
    float x, y;
    asm("mov.b64 {%0,%1}, %2;" : "=f"(x), "=f"(y) : "l"(a));
    return make_float2(x, y);
}

// ---------------------------------------------------------------------------
// dtype probe: int64 story => odd 32-bit words (high halves) are all zero.
// ---------------------------------------------------------------------------
__global__ void detect_kernel(const unsigned int* __restrict__ s) {
    unsigned int acc = 0;
    #pragma unroll
    for (int i = threadIdx.x; i < 256; i += 32) acc |= s[2 * i + 1];
    #pragma unroll
    for (int o = 16; o; o >>= 1) acc |= __shfl_xor_sync(0xffffffffu, acc, o);
    if (threadIdx.x == 0) g_is64 = (acc == 0) ? 1 : 0;
}

// ---------------------------------------------------------------------------
// Zero helpers
// ---------------------------------------------------------------------------
__global__ void zero_w_kernel() {
    int i = blockIdx.x * blockDim.x + threadIdx.x;   // 3125*256 = 800000 float4
    float4 z = make_float4(0.f, 0.f, 0.f, 0.f);
    *(float4*)&g_w[(size_t)i * 4] = z;
}

__global__ void zero_u_kernel(float* u) {
    int i = blockIdx.x * blockDim.x + threadIdx.x;   // 32*256 = 8192
    u[i] = 0.f;
}

// ---------------------------------------------------------------------------
// Fused: scores via p-gather, softmax over M, scatter prob into g_w.
// One block per batch b (64 blocks, 256 threads, 8 m per thread).
// hop 0 (use_p==0): uniform prob = 1/M, no score/softmax phase.
// Story may be int64 or int32 (JAX x64 demotion) -> branch on g_is64.
// ---------------------------------------------------------------------------
__global__ __launch_bounds__(256) void fused_attn(const void* __restrict__ story,
                                                  int use_p) {
    int b = blockIdx.x;
    int tid = threadIdx.x;
    __shared__ float red[8];

    int is64 = g_is64;
    int toks[8][4];
    float sc[8];
    const float* pb = g_p + (size_t)b * VV;

    #pragma unroll
    for (int i = 0; i < 8; i++) {
        int m = tid + i * 256;
        if (is64) {
            const long long* sp = (const long long*)story + (size_t)m * (BB * TT) + b * TT;
            longlong2 t0 = ((const longlong2*)sp)[0];
            longlong2 t1 = ((const longlong2*)sp)[1];
            toks[i][0] = (int)t0.x; toks[i][1] = (int)t0.y;
            toks[i][2] = (int)t1.x; toks[i][3] = (int)t1.y;
        } else {
            int4 tt = *((const int4*)((const int*)story + (size_t)m * (BB * TT) + b * TT));
            toks[i][0] = tt.x; toks[i][1] = tt.y;
            toks[i][2] = tt.z; toks[i][3] = tt.w;
        }
        float s = 0.f;
        if (use_p) {
            #pragma unroll
            for (int t = 0; t < 4; t++)
                if (toks[i][t]) s += __ldg(&pb[toks[i][t]]);
        }
        sc[i] = s;
    }

    float prob[8];
    if (use_p) {
        // block max
        float mx = sc[0];
        #pragma unroll
        for (int i = 1; i < 8; i++) mx = fmaxf(mx, sc[i]);
        #pragma unroll
        for (int o = 16; o; o >>= 1) mx = fmaxf(mx, __shfl_xor_sync(0xffffffffu, mx, o));
        if ((tid & 31) == 0) red[tid >> 5] = mx;
        __syncthreads();
        float bm = red[0];
        #pragma unroll
        for (int i = 1; i < 8; i++) bm = fmaxf(bm, red[i]);
        // exp + block sum
        float sum = 0.f;
        #pragma unroll
        for (int i = 0; i < 8; i++) { float e = __expf(sc[i] - bm); sc[i] = e; sum += e; }
        #pragma unroll
        for (int o = 16; o; o >>= 1) sum += __shfl_xor_sync(0xffffffffu, sum, o);
        __syncthreads();   // everyone done reading red (max phase)
        if ((tid & 31) == 0) red[tid >> 5] = sum;
        __syncthreads();
        float tot = 0.f;
        #pragma unroll
        for (int i = 0; i < 8; i++) tot += red[i];
        float inv = 1.f / tot;
        #pragma unroll
        for (int i = 0; i < 8; i++) prob[i] = sc[i] * inv;
    } else {
        #pragma unroll
        for (int i = 0; i < 8; i++) prob[i] = 1.0f / (float)MM;
    }

    float* wb = g_w + (size_t)b * VV;
    #pragma unroll
    for (int i = 0; i < 8; i++) {
        #pragma unroll
        for (int t = 0; t < 4; t++)
            if (toks[i][t]) atomicAdd(&wb[toks[i][t]], prob[i]);
    }
}

// ---------------------------------------------------------------------------
// p = u @ C^T :  p[b][v] = sum_d u[b][d] * Ct[v][d]
// Block: 128 vocab rows x 64 b, K=128 in 4 tiles of 32.
// ---------------------------------------------------------------------------
__global__ __launch_bounds__(256) void p_gemm(const float* __restrict__ Ct,
                                              const float* __restrict__ u) {
    __shared__ float Cs[128][33];   // [v][k], pad 33 -> conflict-free lane-v reads
    __shared__ float us[32][64];    // [k][b] transposed slice of u

    int tid = threadIdx.x;
    int vlane = tid & 31;
    int bg = tid >> 5;
    int vbase = blockIdx.x * 128;

    ull acc[4][4];
    #pragma unroll
    for (int a = 0; a < 4; a++)
        #pragma unroll
        for (int c = 0; c < 4; c++) acc[a][c] = pack2(0.f, 0.f);

    #pragma unroll 1
    for (int kt = 0; kt < 4; kt++) {
        __syncthreads();
        // stage Cs: 128 rows x 32 k
        {
            int r = tid >> 1, part = tid & 1;
            int v = vbase + r;
            const float* src = Ct + (size_t)v * DD + kt * 32 + part * 16;
            #pragma unroll
            for (int q = 0; q < 4; q++) {
                float4 f = make_float4(0.f, 0.f, 0.f, 0.f);
                if (v < VV) f = *(const float4*)(src + q * 4);
                Cs[r][part * 16 + q * 4 + 0] = f.x;
                Cs[r][part * 16 + q * 4 + 1] = f.y;
                Cs[r][part * 16 + q * 4 + 2] = f.z;
                Cs[r][part * 16 + q * 4 + 3] = f.w;
            }
        }
        // stage us[k][b]
        {
            int b_ = tid & 63;
            int kh = tid >> 6;   // 0..3
            #pragma unroll
            for (int kk = 0; kk < 8; kk++) {
                int k = kh * 8 + kk;
                us[k][b_] = u[b_ * DD + kt * 32 + k];
            }
        }
        __syncthreads();

        #pragma unroll 4
        for (int k = 0; k < 32; k++) {
            ull up[4];
            #pragma unroll
            for (int pp = 0; pp < 4; pp++)
                up[pp] = *(const ull*)&us[k][bg * 8 + pp * 2];
            #pragma unroll
            for (int j = 0; j < 4; j++) {
                float c = Cs[vlane + 32 * j][k];
                ull c2 = pack2(c, c);
                #pragma unroll
                for (int pp = 0; pp < 4; pp++)
                    acc[pp][j] = fma2(up[pp], c2, acc[pp][j]);
            }
        }
    }

    // store: coalesced across lanes (lanes vary v contiguously)
    #pragma unroll
    for (int pp = 0; pp < 4; pp++) {
        #pragma unroll
        for (int j = 0; j < 4; j++) {
            int vv = vbase + vlane + 32 * j;
            if (vv < VV) {
                float2 xy = unpack2(acc[pp][j]);
                int b0 = bg * 8 + pp * 2;
                g_p[(size_t)b0 * VV + vv] = xy.x;
                g_p[(size_t)(b0 + 1) * VV + vv] = xy.y;
            }
        }
    }
}

// ---------------------------------------------------------------------------
// o_partial = w @ C :  o[b][d] = sum_v w[b][v] * Ct[v][d]
// Grid: 143 blocks, each a 352-row K-chunk (11 tiles of 32).
// ---------------------------------------------------------------------------
__global__ __launch_bounds__(256) void o_gemm(const float* __restrict__ Ct) {
    __shared__ float Cs[32][128];     // [v][d]
    __shared__ float2 wsd[32][64];    // [v][b] pre-duplicated {w,w}

    int tid = threadIdx.x;
    int dlane = tid & 31;
    int bg = tid >> 5;
    int vstart = blockIdx.x * OG_CHUNK;

    ull acc[8][2];
    #pragma unroll
    for (int i = 0; i < 8; i++) { acc[i][0] = pack2(0.f, 0.f); acc[i][1] = pack2(0.f, 0.f); }

    #pragma unroll 1
    for (int t = 0; t < 11; t++) {
        int vb = vstart + t * 32;
        __syncthreads();
        // stage Cs (coalesced float4)
        #pragma unroll
        for (int q = 0; q < 4; q++) {
            int fi = tid + q * 256;
            int r = fi >> 5, c4 = fi & 31;
            int v = vb + r;
            float4 f = make_float4(0.f, 0.f, 0.f, 0.f);
            if (v < VV) f = *(const float4*)(Ct + (size_t)v * DD + c4 * 4);
            *(float4*)&Cs[r][c4 * 4] = f;
        }
        // stage wsd
        #pragma unroll
        for (int q = 0; q < 2; q++) {
            int fi = tid + q * 256;
            int v4 = fi >> 6, b_ = fi & 63;
            int v = vb + v4 * 4;
            float4 f = make_float4(0.f, 0.f, 0.f, 0.f);
            if (v + 3 < VV) {
                f = *(const float4*)(g_w + (size_t)b_ * VV + v);
            } else {
                if (v + 0 < VV) f.x = g_w[(size_t)b_ * VV + v + 0];
                if (v + 1 < VV) f.y = g_w[(size_t)b_ * VV + v + 1];
                if (v + 2 < VV) f.z = g_w[(size_t)b_ * VV + v + 2];
                if (v + 3 < VV) f.w = g_w[(size_t)b_ * VV + v + 3];
            }
            wsd[v4 * 4 + 0][b_] = make_float2(f.x, f.x);
            wsd[v4 * 4 + 1][b_] = make_float2(f.y, f.y);
            wsd[v4 * 4 + 2][b_] = make_float2(f.z, f.z);
            wsd[v4 * 4 + 3][b_] = make_float2(f.w, f.w);
        }
        __syncthreads();

        #pragma unroll 4
        for (int v = 0; v < 32; v++) {
            ulonglong2 cc = *(const ulonglong2*)&Cs[v][dlane * 4];
            #pragma unroll
            for (int i = 0; i < 8; i++) {
                ull wv = *(const ull*)&wsd[v][bg * 8 + i];
                acc[i][0] = fma2(wv, cc.x, acc[i][0]);
                acc[i][1] = fma2(wv, cc.y, acc[i][1]);
            }
        }
    }

    float* op = g_opart + (size_t)blockIdx.x * (BB * DD);
    #pragma unroll
    for (int i = 0; i < 8; i++) {
        int b_ = bg * 8 + i;
        *(ull*)&op[b_ * DD + dlane * 4]     = acc[i][0];
        *(ull*)&op[b_ * DD + dlane * 4 + 2] = acc[i][1];
    }
}

// u[i] += sum over blocks of g_opart[blk][i]
__global__ __launch_bounds__(256) void reduce_opart(float* __restrict__ u) {
    int i = blockIdx.x * 256 + threadIdx.x;   // 32*256 = 8192
    float s = u[i];
    #pragma unroll 4
    for (int k = 0; k < OG_GRID; k++) s += g_opart[(size_t)k * (BB * DD) + i];
    u[i] = s;
}

// ---------------------------------------------------------------------------
extern "C" void kernel_launch(void* const* d_in, const int* in_sizes, int n_in,
                              void* d_out, int out_size) {
    // story is the smaller input (524288 elems), C the larger (25.6M fp32)
    int si = 0, ci = 1;
    if (n_in >= 2 && in_sizes[0] > in_sizes[1]) { si = 1; ci = 0; }
    const void* story = d_in[si];
    const float* C = (const float*)d_in[ci];
    float* u = (float*)d_out;

    detect_kernel<<<1, 32>>>((const unsigned int*)story);
    zero_u_kernel<<<32, 256>>>(u);

    for (int h = 0; h < 3; h++) {
        if (h) p_gemm<<<PG_GRID, 256>>>(C + (size_t)h * VV * DD, u);
        zero_w_kernel<<<3125, 256>>>();
        fused_attn<<<BB, 256>>>(story, h > 0 ? 1 : 0);
        o_gemm<<<OG_GRID, 256>>>(C + (size_t)(h + 1) * VV * DD);
        reduce_opart<<<32, 256>>>(u);
    }
}

// round 4
// speedup vs baseline: 1.1861x; 1.1861x over previous
#include <cuda_runtime.h>
#include <math.h>

#define MM 2048
#define BB 64
#define TT 4
#define DD 128
#define VV 50000

#define PG_GRID 391          // ceil(50000/128)
#define OG_GRID 261          // 261*192 = 50112 >= 50000
#define OG_TILES 6
#define CST_STRIDE 132       // 128 + 4 pad, keeps 16B alignment

// Scratch (device globals: allocation-free rule). 16B-aligned for vector access.
__device__ __align__(16) float g_w[BB * VV];   // scatter weights  [b][v]
__device__ __align__(16) float g_p[BB * VV];   // p = C[h] @ u^T   [b][v]
__device__ int g_is64;                         // story dtype flag

typedef unsigned long long ull;

__device__ __forceinline__ ull pack2(float x, float y) {
    ull r;
    asm("mov.b64 %0, {%1,%2};" : "=l"(r) : "f"(x), "f"(y));
    return r;
}
__device__ __forceinline__ ull fma2(ull a, ull b, ull c) {
    ull d;
    asm("fma.rn.f32x2 %0, %1, %2, %3;" : "=l"(d) : "l"(a), "l"(b), "l"(c));
    return d;
}
__device__ __forceinline__ float2 unpack2(ull a) {
    float x, y;
    asm("mov.b64 {%0,%1}, %2;" : "=f"(x), "=f"(y) : "l"(a));
    return make_float2(x, y);
}

// ---------------------------------------------------------------------------
// dtype probe: int64 story => odd 32-bit words (high halves) are all zero.
// ---------------------------------------------------------------------------
__global__ void detect_kernel(const unsigned int* __restrict__ s) {
    unsigned int acc = 0;
    #pragma unroll
    for (int i = threadIdx.x; i < 256; i += 32) acc |= s[2 * i + 1];
    #pragma unroll
    for (int o = 16; o; o >>= 1) acc |= __shfl_xor_sync(0xffffffffu, acc, o);
    if (threadIdx.x == 0) g_is64 = (acc == 0) ? 1 : 0;
}

__global__ void zero_u_kernel(float* u) {
    int i = blockIdx.x * blockDim.x + threadIdx.x;   // 32*256 = 8192
    u[i] = 0.f;
}

// ---------------------------------------------------------------------------
// Fused: zero w[b] row, scores via p-gather, softmax over M, scatter into g_w.
// One block per batch b (64 blocks, 256 threads, 8 m per thread).
// ---------------------------------------------------------------------------
__global__ __launch_bounds__(256) void fused_attn(const void* __restrict__ story,
                                                  int use_p) {
    int b = blockIdx.x;
    int tid = threadIdx.x;
    __shared__ float red[8];

    float* wb = g_w + (size_t)b * VV;

    // zero this block's exclusive w row (replaces zero_w kernel)
    {
        float4 z = make_float4(0.f, 0.f, 0.f, 0.f);
        for (int i = tid; i < VV / 4; i += 256)
            *(float4*)&wb[i * 4] = z;
    }

    int is64 = g_is64;
    int toks[8][4];
    float sc[8];
    const float* pb = g_p + (size_t)b * VV;

    #pragma unroll
    for (int i = 0; i < 8; i++) {
        int m = tid + i * 256;
        if (is64) {
            const long long* sp = (const long long*)story + (size_t)m * (BB * TT) + b * TT;
            longlong2 t0 = ((const longlong2*)sp)[0];
            longlong2 t1 = ((const longlong2*)sp)[1];
            toks[i][0] = (int)t0.x; toks[i][1] = (int)t0.y;
            toks[i][2] = (int)t1.x; toks[i][3] = (int)t1.y;
        } else {
            int4 tt = *((const int4*)((const int*)story + (size_t)m * (BB * TT) + b * TT));
            toks[i][0] = tt.x; toks[i][1] = tt.y;
            toks[i][2] = tt.z; toks[i][3] = tt.w;
        }
        float s = 0.f;
        if (use_p) {
            #pragma unroll
            for (int t = 0; t < 4; t++)
                if (toks[i][t]) s += __ldg(&pb[toks[i][t]]);
        }
        sc[i] = s;
    }

    // ensures: zero stores visible block-wide before any scatter below
    __syncthreads();

    float prob[8];
    if (use_p) {
        float mx = sc[0];
        #pragma unroll
        for (int i = 1; i < 8; i++) mx = fmaxf(mx, sc[i]);
        #pragma unroll
        for (int o = 16; o; o >>= 1) mx = fmaxf(mx, __shfl_xor_sync(0xffffffffu, mx, o));
        if ((tid & 31) == 0) red[tid >> 5] = mx;
        __syncthreads();
        float bm = red[0];
        #pragma unroll
        for (int i = 1; i < 8; i++) bm = fmaxf(bm, red[i]);
        float sum = 0.f;
        #pragma unroll
        for (int i = 0; i < 8; i++) { float e = __expf(sc[i] - bm); sc[i] = e; sum += e; }
        #pragma unroll
        for (int o = 16; o; o >>= 1) sum += __shfl_xor_sync(0xffffffffu, sum, o);
        __syncthreads();
        if ((tid & 31) == 0) red[tid >> 5] = sum;
        __syncthreads();
        float tot = 0.f;
        #pragma unroll
        for (int i = 0; i < 8; i++) tot += red[i];
        float inv = 1.f / tot;
        #pragma unroll
        for (int i = 0; i < 8; i++) prob[i] = sc[i] * inv;
    } else {
        #pragma unroll
        for (int i = 0; i < 8; i++) prob[i] = 1.0f / (float)MM;
    }

    #pragma unroll
    for (int i = 0; i < 8; i++) {
        #pragma unroll
        for (int t = 0; t < 4; t++)
            if (toks[i][t]) atomicAdd(&wb[toks[i][t]], prob[i]);
    }
}

// ---------------------------------------------------------------------------
// p = u @ C^T :  p[b][v] = sum_k u[b][k] * Ct[v][k]
// One full-K tile per block: 128 v x 128 k, no inner syncs.
// smem: Cst[k][v] (transposed, LDS.128 over 4 adjacent v), us[k][b].
// Thread: vlane=tid&31 -> v=vbase+vlane*4..+3; bg=tid>>5 -> 8 b as 4 pairs.
// ---------------------------------------------------------------------------
__global__ __launch_bounds__(256, 2) void p_gemm(const float* __restrict__ Ct,
                                                 const float* __restrict__ u) {
    extern __shared__ float sm[];
    float* Cst = sm;                        // [128][CST_STRIDE]
    float* us  = sm + 128 * CST_STRIDE;     // [128][64]

    int tid = threadIdx.x;
    int vlane = tid & 31;
    int bg = tid >> 5;
    int vbase = blockIdx.x * 128;

    // stage Cst: coalesced LDG.128, transposed scalar STS
    #pragma unroll
    for (int q = 0; q < 16; q++) {
        int fi = tid + q * 256;
        int r = fi >> 5;          // v in tile
        int c4 = fi & 31;         // float4 index along k
        int v = vbase + r;
        float4 f = make_float4(0.f, 0.f, 0.f, 0.f);
        if (v < VV) f = *(const float4*)(Ct + (size_t)v * DD + c4 * 4);
        Cst[(c4 * 4 + 0) * CST_STRIDE + r] = f.x;
        Cst[(c4 * 4 + 1) * CST_STRIDE + r] = f.y;
        Cst[(c4 * 4 + 2) * CST_STRIDE + r] = f.z;
        Cst[(c4 * 4 + 3) * CST_STRIDE + r] = f.w;
    }
    // stage us[k][b] (u: 32 KB, L2 resident)
    #pragma unroll
    for (int q = 0; q < 8; q++) {
        int fi = tid + q * 256;
        int b_ = fi >> 5;
        int k4 = fi & 31;
        float4 f = *(const float4*)(u + b_ * DD + k4 * 4);
        us[(k4 * 4 + 0) * 64 + b_] = f.x;
        us[(k4 * 4 + 1) * 64 + b_] = f.y;
        us[(k4 * 4 + 2) * 64 + b_] = f.z;
        us[(k4 * 4 + 3) * 64 + b_] = f.w;
    }
    __syncthreads();

    ull acc[4][4];   // [j: v in float4][pp: b-pair]
    #pragma unroll
    for (int j = 0; j < 4; j++)
        #pragma unroll
        for (int pp = 0; pp < 4; pp++) acc[j][pp] = pack2(0.f, 0.f);

    #pragma unroll 4
    for (int k = 0; k < 128; k++) {
        float4 c = *(const float4*)&Cst[k * CST_STRIDE + vlane * 4];
        ull up[4];
        #pragma unroll
        for (int pp = 0; pp < 4; pp++)
            up[pp] = *(const ull*)&us[k * 64 + bg * 8 + pp * 2];   // broadcast
        ull c2[4];
        c2[0] = pack2(c.x, c.x); c2[1] = pack2(c.y, c.y);
        c2[2] = pack2(c.z, c.z); c2[3] = pack2(c.w, c.w);
        #pragma unroll
        for (int j = 0; j < 4; j++)
            #pragma unroll
            for (int pp = 0; pp < 4; pp++)
                acc[j][pp] = fma2(up[pp], c2[j], acc[j][pp]);
    }

    // output: per (b, pair-half) assemble float4 over 4 adjacent v -> STG.128
    int v0 = vbase + vlane * 4;
    if (v0 < VV) {
        #pragma unroll
        for (int pp = 0; pp < 4; pp++) {
            int b0 = bg * 8 + pp * 2;
            float2 e0 = unpack2(acc[0][pp]);
            float2 e1 = unpack2(acc[1][pp]);
            float2 e2 = unpack2(acc[2][pp]);
            float2 e3 = unpack2(acc[3][pp]);
            float4 f0 = make_float4(e0.x, e1.x, e2.x, e3.x);
            float4 f1 = make_float4(e0.y, e1.y, e2.y, e3.y);
            *(float4*)&g_p[(size_t)b0 * VV + v0]       = f0;
            *(float4*)&g_p[(size_t)(b0 + 1) * VV + v0] = f1;
        }
    }
}

// ---------------------------------------------------------------------------
// u += w @ C :  u[b][d] += sum_v w[b][v] * Ct[v][d]   (RED.F32 into u)
// Grid 261 blocks x 6 tiles of 32 v, register-double-buffered staging.
// Thread: dlane=tid&31 -> d=dlane*4..+3 (2 f32x2 d-pairs); bg -> 8 b.
// ---------------------------------------------------------------------------
__global__ __launch_bounds__(256, 2) void o_gemm(const float* __restrict__ Ct,
                                                 float* __restrict__ u) {
    __shared__ float Cs[32][128];     // [v][d]
    __shared__ float2 wsd[32][64];    // [v][b] pre-duplicated {w,w}

    int tid = threadIdx.x;
    int dlane = tid & 31;
    int bg = tid >> 5;
    int vstart = blockIdx.x * (OG_TILES * 32);

    // staging index precompute
    int sr  = tid >> 5, sc4 = tid & 31;        // Cs: 4 float4/thread (q rows +8)
    int sv4 = tid >> 6, sb = tid & 63;         // wsd: 2 float4/thread (q v4 +4)

    float4 rc[4], rw[2];

    // prefetch tile 0
    {
        int vb = vstart;
        #pragma unroll
        for (int q = 0; q < 4; q++) {
            int v = vb + sr + q * 8;
            rc[q] = make_float4(0.f, 0.f, 0.f, 0.f);
            if (v < VV) rc[q] = *(const float4*)(Ct + (size_t)v * DD + sc4 * 4);
        }
        #pragma unroll
        for (int q = 0; q < 2; q++) {
            int v = vb + (sv4 + q * 4) * 4;
            rw[q] = make_float4(0.f, 0.f, 0.f, 0.f);
            if (v < VV) rw[q] = *(const float4*)(g_w + (size_t)sb * VV + v);
        }
    }

    ull acc[8][2];
    #pragma unroll
    for (int i = 0; i < 8; i++) { acc[i][0] = pack2(0.f, 0.f); acc[i][1] = pack2(0.f, 0.f); }

    #pragma unroll 1
    for (int t = 0; t < OG_TILES; t++) {
        __syncthreads();
        // commit prefetched regs to shared
        #pragma unroll
        for (int q = 0; q < 4; q++)
            *(float4*)&Cs[sr + q * 8][sc4 * 4] = rc[q];
        #pragma unroll
        for (int q = 0; q < 2; q++) {
            int vr = (sv4 + q * 4) * 4;
            wsd[vr + 0][sb] = make_float2(rw[q].x, rw[q].x);
            wsd[vr + 1][sb] = make_float2(rw[q].y, rw[q].y);
            wsd[vr + 2][sb] = make_float2(rw[q].z, rw[q].z);
            wsd[vr + 3][sb] = make_float2(rw[q].w, rw[q].w);
        }
        __syncthreads();

        // prefetch next tile (hidden behind compute below)
        if (t + 1 < OG_TILES) {
            int vb = vstart + (t + 1) * 32;
            #pragma unroll
            for (int q = 0; q < 4; q++) {
                int v = vb + sr + q * 8;
                rc[q] = make_float4(0.f, 0.f, 0.f, 0.f);
                if (v < VV) rc[q] = *(const float4*)(Ct + (size_t)v * DD + sc4 * 4);
            }
            #pragma unroll
            for (int q = 0; q < 2; q++) {
                int v = vb + (sv4 + q * 4) * 4;
                rw[q] = make_float4(0.f, 0.f, 0.f, 0.f);
                if (v < VV) rw[q] = *(const float4*)(g_w + (size_t)sb * VV + v);
            }
        }

        #pragma unroll 4
        for (int v = 0; v < 32; v++) {
            ulonglong2 cc = *(const ulonglong2*)&Cs[v][dlane * 4];
            #pragma unroll
            for (int i = 0; i < 8; i++) {
                ull wv = *(const ull*)&wsd[v][bg * 8 + i];   // broadcast
                acc[i][0] = fma2(wv, cc.x, acc[i][0]);
                acc[i][1] = fma2(wv, cc.y, acc[i][1]);
            }
        }
    }

    // RED directly into u (no partials, no reduce kernel)
    #pragma unroll
    for (int i = 0; i < 8; i++) {
        int b_ = bg * 8 + i;
        float2 a0 = unpack2(acc[i][0]);
        float2 a1 = unpack2(acc[i][1]);
        atomicAdd(&u[b_ * DD + dlane * 4 + 0], a0.x);
        atomicAdd(&u[b_ * DD + dlane * 4 + 1], a0.y);
        atomicAdd(&u[b_ * DD + dlane * 4 + 2], a1.x);
        atomicAdd(&u[b_ * DD + dlane * 4 + 3], a1.y);
    }
}

// ---------------------------------------------------------------------------
extern "C" void kernel_launch(void* const* d_in, const int* in_sizes, int n_in,
                              void* d_out, int out_size) {
    int si = 0, ci = 1;
    if (n_in >= 2 && in_sizes[0] > in_sizes[1]) { si = 1; ci = 0; }
    const void* story = d_in[si];
    const float* C = (const float*)d_in[ci];
    float* u = (float*)d_out;

    static int smem_set = 0;
    const int PG_SMEM = (128 * CST_STRIDE + 128 * 64) * 4;   // 100352 B
    if (!smem_set) {
        cudaFuncSetAttribute(p_gemm, cudaFuncAttributeMaxDynamicSharedMemorySize, PG_SMEM);
        smem_set = 1;
    }

    detect_kernel<<<1, 32>>>((const unsigned int*)story);
    zero_u_kernel<<<32, 256>>>(u);

    for (int h = 0; h < 3; h++) {
        if (h) p_gemm<<<PG_GRID, 256, PG_SMEM>>>(C + (size_t)h * VV * DD, u);
        fused_attn<<<BB, 256>>>(story, h > 0 ? 1 : 0);
        o_gemm<<<OG_GRID, 256>>>(C + (size_t)(h + 1) * VV * DD, u);
    }
}

// round 5
// speedup vs baseline: 1.3428x; 1.1320x over previous
#include <cuda_runtime.h>
#include <math.h>

#define MM 2048
#define BB 64
#define TT 4
#define DD 128
#define VV 50000

#define PG_GRID 391          // ceil(50000/128)
#define OG_GRID 261          // 261*192 = 50112 >= 50000
#define OG_TILES 6
#define CST_STRIDE 132       // 128 + 4 pad, keeps 16B alignment

// Scratch (device globals: allocation-free rule). 16B-aligned for vector access.
__device__ __align__(16) float g_w[BB * VV];   // scatter weights  [b][v]
__device__ __align__(16) float g_p[BB * VV];   // p = C[h] @ u^T   [b][v]
__device__ int g_is64;                         // story dtype flag

typedef unsigned long long ull;

__device__ __forceinline__ ull pack2(float x, float y) {
    ull r;
    asm("mov.b64 %0, {%1,%2};" : "=l"(r) : "f"(x), "f"(y));
    return r;
}
__device__ __forceinline__ ull fma2(ull a, ull b, ull c) {
    ull d;
    asm("fma.rn.f32x2 %0, %1, %2, %3;" : "=l"(d) : "l"(a), "l"(b), "l"(c));
    return d;
}
__device__ __forceinline__ float2 unpack2(ull a) {
    float x, y;
    asm("mov.b64 {%0,%1}, %2;" : "=f"(x), "=f"(y) : "l"(a));
    return make_float2(x, y);
}

// ---------------------------------------------------------------------------
// Prologue: zero g_w (blocks 0..3124), zero u (block 3125), dtype probe (3126)
// ---------------------------------------------------------------------------
__global__ __launch_bounds__(256) void prologue(const unsigned int* __restrict__ s,
                                                float* __restrict__ u) {
    int blk = blockIdx.x;
    int tid = threadIdx.x;
    if (blk < 3125) {
        int i = blk * 256 + tid;                 // 800000 float4 = 3.2M floats
        float4 z = make_float4(0.f, 0.f, 0.f, 0.f);
        *(float4*)&g_w[(size_t)i * 4] = z;
    } else if (blk == 3125) {
        for (int i = tid; i < BB * DD; i += 256) u[i] = 0.f;
    } else if (tid < 32) {
        unsigned int acc = 0;
        #pragma unroll
        for (int i = tid; i < 256; i += 32) acc |= s[2 * i + 1];
        #pragma unroll
        for (int o = 16; o; o >>= 1) acc |= __shfl_xor_sync(0xffffffffu, acc, o);
        if (tid == 0) g_is64 = (acc == 0) ? 1 : 0;
    }
}

// ---------------------------------------------------------------------------
// Fused attention: scores via p-gather, softmax over M, scatter prob into g_w.
// One block per batch b (64 blocks, 512 threads, 4 m per thread).
// g_w must be pre-zeroed (prologue / previous o_gemm).
// ---------------------------------------------------------------------------
__global__ __launch_bounds__(512) void fused_attn(const void* __restrict__ story,
                                                  int use_p) {
    int b = blockIdx.x;
    int tid = threadIdx.x;
    __shared__ float red[16];

    float* wb = g_w + (size_t)b * VV;
    int is64 = g_is64;
    int toks[4][4];
    float sc[4];
    const float* pb = g_p + (size_t)b * VV;

    #pragma unroll
    for (int i = 0; i < 4; i++) {
        int m = tid + i * 512;
        if (is64) {
            const long long* sp = (const long long*)story + (size_t)m * (BB * TT) + b * TT;
            longlong2 t0 = ((const longlong2*)sp)[0];
            longlong2 t1 = ((const longlong2*)sp)[1];
            toks[i][0] = (int)t0.x; toks[i][1] = (int)t0.y;
            toks[i][2] = (int)t1.x; toks[i][3] = (int)t1.y;
        } else {
            int4 tt = *((const int4*)((const int*)story + (size_t)m * (BB * TT) + b * TT));
            toks[i][0] = tt.x; toks[i][1] = tt.y;
            toks[i][2] = tt.z; toks[i][3] = tt.w;
        }
        float s = 0.f;
        if (use_p) {
            #pragma unroll
            for (int t = 0; t < 4; t++)
                if (toks[i][t]) s += __ldg(&pb[toks[i][t]]);
        }
        sc[i] = s;
    }

    float prob[4];
    if (use_p) {
        float mx = fmaxf(fmaxf(sc[0], sc[1]), fmaxf(sc[2], sc[3]));
        #pragma unroll
        for (int o = 16; o; o >>= 1) mx = fmaxf(mx, __shfl_xor_sync(0xffffffffu, mx, o));
        if ((tid & 31) == 0) red[tid >> 5] = mx;
        __syncthreads();
        float bm = red[0];
        #pragma unroll
        for (int i = 1; i < 16; i++) bm = fmaxf(bm, red[i]);
        float sum = 0.f;
        #pragma unroll
        for (int i = 0; i < 4; i++) { float e = __expf(sc[i] - bm); sc[i] = e; sum += e; }
        #pragma unroll
        for (int o = 16; o; o >>= 1) sum += __shfl_xor_sync(0xffffffffu, sum, o);
        __syncthreads();
        if ((tid & 31) == 0) red[tid >> 5] = sum;
        __syncthreads();
        float tot = 0.f;
        #pragma unroll
        for (int i = 0; i < 16; i++) tot += red[i];
        float inv = 1.f / tot;
        #pragma unroll
        for (int i = 0; i < 4; i++) prob[i] = sc[i] * inv;
    } else {
        #pragma unroll
        for (int i = 0; i < 4; i++) prob[i] = 1.0f / (float)MM;
    }

    #pragma unroll
    for (int i = 0; i < 4; i++) {
        #pragma unroll
        for (int t = 0; t < 4; t++)
            if (toks[i][t]) atomicAdd(&wb[toks[i][t]], prob[i]);
    }
}

// ---------------------------------------------------------------------------
// p = u @ C^T :  p[b][v] = sum_k u[b][k] * Ct[v][k]
// One full-K tile per block: 128 v x 128 k, no inner syncs.
// ---------------------------------------------------------------------------
__global__ __launch_bounds__(256, 2) void p_gemm(const float* __restrict__ Ct,
                                                 const float* __restrict__ u) {
    extern __shared__ float sm[];
    float* Cst = sm;                        // [128][CST_STRIDE]
    float* us  = sm + 128 * CST_STRIDE;     // [128][64]

    int tid = threadIdx.x;
    int vlane = tid & 31;
    int bg = tid >> 5;
    int vbase = blockIdx.x * 128;

    // stage Cst: coalesced LDG.128, transposed scalar STS
    #pragma unroll
    for (int q = 0; q < 16; q++) {
        int fi = tid + q * 256;
        int r = fi >> 5;          // v in tile
        int c4 = fi & 31;         // float4 index along k
        int v = vbase + r;
        float4 f = make_float4(0.f, 0.f, 0.f, 0.f);
        if (v < VV) f = *(const float4*)(Ct + (size_t)v * DD + c4 * 4);
        Cst[(c4 * 4 + 0) * CST_STRIDE + r] = f.x;
        Cst[(c4 * 4 + 1) * CST_STRIDE + r] = f.y;
        Cst[(c4 * 4 + 2) * CST_STRIDE + r] = f.z;
        Cst[(c4 * 4 + 3) * CST_STRIDE + r] = f.w;
    }
    // stage us[k][b]
    #pragma unroll
    for (int q = 0; q < 8; q++) {
        int fi = tid + q * 256;
        int b_ = fi >> 5;
        int k4 = fi & 31;
        float4 f = *(const float4*)(u + b_ * DD + k4 * 4);
        us[(k4 * 4 + 0) * 64 + b_] = f.x;
        us[(k4 * 4 + 1) * 64 + b_] = f.y;
        us[(k4 * 4 + 2) * 64 + b_] = f.z;
        us[(k4 * 4 + 3) * 64 + b_] = f.w;
    }
    __syncthreads();

    ull acc[4][4];   // [j: v in float4][pp: b-pair]
    #pragma unroll
    for (int j = 0; j < 4; j++)
        #pragma unroll
        for (int pp = 0; pp < 4; pp++) acc[j][pp] = pack2(0.f, 0.f);

    #pragma unroll 4
    for (int k = 0; k < 128; k++) {
        float4 c = *(const float4*)&Cst[k * CST_STRIDE + vlane * 4];
        // 8 b's via two broadcast LDS.128
        ulonglong2 ua = *(const ulonglong2*)&us[k * 64 + bg * 8];
        ulonglong2 ub = *(const ulonglong2*)&us[k * 64 + bg * 8 + 4];
        ull up[4];
        up[0] = ua.x; up[1] = ua.y; up[2] = ub.x; up[3] = ub.y;
        ull c2[4];
        c2[0] = pack2(c.x, c.x); c2[1] = pack2(c.y, c.y);
        c2[2] = pack2(c.z, c.z); c2[3] = pack2(c.w, c.w);
        #pragma unroll
        for (int j = 0; j < 4; j++)
            #pragma unroll
            for (int pp = 0; pp < 4; pp++)
                acc[j][pp] = fma2(up[pp], c2[j], acc[j][pp]);
    }

    // output: per (b, pair-half) assemble float4 over 4 adjacent v -> STG.128
    int v0 = vbase + vlane * 4;
    if (v0 < VV) {
        #pragma unroll
        for (int pp = 0; pp < 4; pp++) {
            int b0 = bg * 8 + pp * 2;
            float2 e0 = unpack2(acc[0][pp]);
            float2 e1 = unpack2(acc[1][pp]);
            float2 e2 = unpack2(acc[2][pp]);
            float2 e3 = unpack2(acc[3][pp]);
            float4 f0 = make_float4(e0.x, e1.x, e2.x, e3.x);
            float4 f1 = make_float4(e0.y, e1.y, e2.y, e3.y);
            *(float4*)&g_p[(size_t)b0 * VV + v0]       = f0;
            *(float4*)&g_p[(size_t)(b0 + 1) * VV + v0] = f1;
        }
    }
}

// ---------------------------------------------------------------------------
// u += w @ C :  u[b][d] += sum_v w[b][v] * Ct[v][d]   (RED.F32 into u)
// Grid 261 blocks x 6 tiles of 32 v, register-double-buffered staging.
// Inner loop: 2 broadcast LDS.128 (8 b of w) + 1 LDS.128 (4 d of C),
// C duplicated to f32x2 via ALU; 16 fma2. Then zero own w chunk (next hop).
// ---------------------------------------------------------------------------
__global__ __launch_bounds__(256, 2) void o_gemm(const float* __restrict__ Ct,
                                                 float* __restrict__ u,
                                                 int do_zero) {
    __shared__ float Cs[32][128];     // [v][d]
    __shared__ float ws[32][64];      // [v][b] plain

    int tid = threadIdx.x;
    int dlane = tid & 31;
    int bg = tid >> 5;
    int vstart = blockIdx.x * (OG_TILES * 32);

    // staging index precompute
    int sr  = tid >> 5, sc4 = tid & 31;        // Cs: 4 float4/thread (q rows +8)
    int sv4 = tid >> 6, sb = tid & 63;         // ws: 2 float4/thread (q v4 +4)

    float4 rc[4], rw[2];

    // prefetch tile 0
    {
        int vb = vstart;
        #pragma unroll
        for (int q = 0; q < 4; q++) {
            int v = vb + sr + q * 8;
            rc[q] = make_float4(0.f, 0.f, 0.f, 0.f);
            if (v < VV) rc[q] = *(const float4*)(Ct + (size_t)v * DD + sc4 * 4);
        }
        #pragma unroll
        for (int q = 0; q < 2; q++) {
            int v = vb + (sv4 + q * 4) * 4;
            rw[q] = make_float4(0.f, 0.f, 0.f, 0.f);
            if (v < VV) rw[q] = *(const float4*)(g_w + (size_t)sb * VV + v);
        }
    }

    ull acc[4][4];   // [bp: b-pair][j: d]
    #pragma unroll
    for (int bp = 0; bp < 4; bp++)
        #pragma unroll
        for (int j = 0; j < 4; j++) acc[bp][j] = pack2(0.f, 0.f);

    #pragma unroll 1
    for (int t = 0; t < OG_TILES; t++) {
        __syncthreads();
        // commit prefetched regs to shared
        #pragma unroll
        for (int q = 0; q < 4; q++)
            *(float4*)&Cs[sr + q * 8][sc4 * 4] = rc[q];
        #pragma unroll
        for (int q = 0; q < 2; q++) {
            int vr = (sv4 + q * 4) * 4;
            ws[vr + 0][sb] = rw[q].x;
            ws[vr + 1][sb] = rw[q].y;
            ws[vr + 2][sb] = rw[q].z;
            ws[vr + 3][sb] = rw[q].w;
        }
        __syncthreads();

        // prefetch next tile (hidden behind compute below)
        if (t + 1 < OG_TILES) {
            int vb = vstart + (t + 1) * 32;
            #pragma unroll
            for (int q = 0; q < 4; q++) {
                int v = vb + sr + q * 8;
                rc[q] = make_float4(0.f, 0.f, 0.f, 0.f);
                if (v < VV) rc[q] = *(const float4*)(Ct + (size_t)v * DD + sc4 * 4);
            }
            #pragma unroll
            for (int q = 0; q < 2; q++) {
                int v = vb + (sv4 + q * 4) * 4;
                rw[q] = make_float4(0.f, 0.f, 0.f, 0.f);
                if (v < VV) rw[q] = *(const float4*)(g_w + (size_t)sb * VV + v);
            }
        }

        #pragma unroll 4
        for (int v = 0; v < 32; v++) {
            ulonglong2 wa = *(const ulonglong2*)&ws[v][bg * 8];       // broadcast
            ulonglong2 wb2 = *(const ulonglong2*)&ws[v][bg * 8 + 4];  // broadcast
            float4 c = *(const float4*)&Cs[v][dlane * 4];
            ull wp[4];
            wp[0] = wa.x; wp[1] = wa.y; wp[2] = wb2.x; wp[3] = wb2.y;
            ull c2[4];
            c2[0] = pack2(c.x, c.x); c2[1] = pack2(c.y, c.y);
            c2[2] = pack2(c.z, c.z); c2[3] = pack2(c.w, c.w);
            #pragma unroll
            for (int bp = 0; bp < 4; bp++)
                #pragma unroll
                for (int j = 0; j < 4; j++)
                    acc[bp][j] = fma2(wp[bp], c2[j], acc[bp][j]);
        }
    }

    // RED directly into u
    #pragma unroll
    for (int bp = 0; bp < 4; bp++) {
        int b0 = bg * 8 + bp * 2;
        #pragma unroll
        for (int j = 0; j < 4; j++) {
            float2 a = unpack2(acc[bp][j]);
            atomicAdd(&u[b0 * DD + dlane * 4 + j], a.x);
            atomicAdd(&u[(b0 + 1) * DD + dlane * 4 + j], a.y);
        }
    }

    // zero own w chunk for the next hop's scatter (chunks disjoint per block)
    if (do_zero) {
        float4 z = make_float4(0.f, 0.f, 0.f, 0.f);
        for (int idx = tid; idx < 64 * 48; idx += 256) {
            int b_ = idx / 48;
            int v = vstart + (idx % 48) * 4;
            if (v < VV)
                *(float4*)&g_w[(size_t)b_ * VV + v] = z;
        }
    }
}

// ---------------------------------------------------------------------------
extern "C" void kernel_launch(void* const* d_in, const int* in_sizes, int n_in,
                              void* d_out, int out_size) {
    int si = 0, ci = 1;
    if (n_in >= 2 && in_sizes[0] > in_sizes[1]) { si = 1; ci = 0; }
    const void* story = d_in[si];
    const float* C = (const float*)d_in[ci];
    float* u = (float*)d_out;

    static int smem_set = 0;
    const int PG_SMEM = (128 * CST_STRIDE + 128 * 64) * 4;   // 100352 B
    if (!smem_set) {
        cudaFuncSetAttribute(p_gemm, cudaFuncAttributeMaxDynamicSharedMemorySize, PG_SMEM);
        smem_set = 1;
    }

    prologue<<<3127, 256>>>((const unsigned int*)story, u);

    for (int h = 0; h < 3; h++) {
        if (h) p_gemm<<<PG_GRID, 256, PG_SMEM>>>(C + (size_t)h * VV * DD, u);
        fused_attn<<<BB, 512>>>(story, h > 0 ? 1 : 0);
        o_gemm<<<OG_GRID, 256>>>(C + (size_t)(h + 1) * VV * DD, u, h < 2 ? 1 : 0);
    }
}

// round 6
// speedup vs baseline: 1.4642x; 1.0905x over previous
#include <cuda_runtime.h>
#include <math.h>

#define MM 2048
#define BB 64
#define TT 4
#define DD 128
#define VV 50000

#define PG_GRID 391          // ceil(50000/128)
#define OG_GRID 261          // 261*192 = 50112 >= 50000
#define OG_TILES 6

// Scratch (device globals: allocation-free rule). 16B-aligned for vector access.
__device__ __align__(16) float g_w[BB * VV];   // scatter weights  [b][v]
__device__ __align__(16) float g_p[BB * VV];   // p = C[h] @ u^T   [b][v]
__device__ int g_is64;                         // story dtype flag

typedef unsigned long long ull;

__device__ __forceinline__ ull pack2(float x, float y) {
    ull r;
    asm("mov.b64 %0, {%1,%2};" : "=l"(r) : "f"(x), "f"(y));
    return r;
}
__device__ __forceinline__ ull fma2(ull a, ull b, ull c) {
    ull d;
    asm("fma.rn.f32x2 %0, %1, %2, %3;" : "=l"(d) : "l"(a), "l"(b), "l"(c));
    return d;
}
__device__ __forceinline__ float2 unpack2(ull a) {
    float x, y;
    asm("mov.b64 {%0,%1}, %2;" : "=f"(x), "=f"(y) : "l"(a));
    return make_float2(x, y);
}

// ---------------------------------------------------------------------------
// Prologue: zero g_w (blocks 0..3124), zero u (block 3125), dtype probe (3126)
// ---------------------------------------------------------------------------
__global__ __launch_bounds__(256) void prologue(const unsigned int* __restrict__ s,
                                                float* __restrict__ u) {
    int blk = blockIdx.x;
    int tid = threadIdx.x;
    if (blk < 3125) {
        int i = blk * 256 + tid;                 // 800000 float4 = 3.2M floats
        float4 z = make_float4(0.f, 0.f, 0.f, 0.f);
        *(float4*)&g_w[(size_t)i * 4] = z;
    } else if (blk == 3125) {
        for (int i = tid; i < BB * DD; i += 256) u[i] = 0.f;
    } else if (tid < 32) {
        unsigned int acc = 0;
        #pragma unroll
        for (int i = tid; i < 256; i += 32) acc |= s[2 * i + 1];
        #pragma unroll
        for (int o = 16; o; o >>= 1) acc |= __shfl_xor_sync(0xffffffffu, acc, o);
        if (tid == 0) g_is64 = (acc == 0) ? 1 : 0;
    }
}

// ---------------------------------------------------------------------------
// Fused attention: scores via p-gather, softmax over M, scatter prob into g_w.
// One block per batch b (64 blocks, 512 threads, 4 m per thread).
// ---------------------------------------------------------------------------
__global__ __launch_bounds__(512) void fused_attn(const void* __restrict__ story,
                                                  int use_p) {
    int b = blockIdx.x;
    int tid = threadIdx.x;
    __shared__ float red[16];

    float* wb = g_w + (size_t)b * VV;
    int is64 = g_is64;
    int toks[4][4];
    float sc[4];
    const float* pb = g_p + (size_t)b * VV;

    #pragma unroll
    for (int i = 0; i < 4; i++) {
        int m = tid + i * 512;
        if (is64) {
            const long long* sp = (const long long*)story + (size_t)m * (BB * TT) + b * TT;
            longlong2 t0 = ((const longlong2*)sp)[0];
            longlong2 t1 = ((const longlong2*)sp)[1];
            toks[i][0] = (int)t0.x; toks[i][1] = (int)t0.y;
            toks[i][2] = (int)t1.x; toks[i][3] = (int)t1.y;
        } else {
            int4 tt = *((const int4*)((const int*)story + (size_t)m * (BB * TT) + b * TT));
            toks[i][0] = tt.x; toks[i][1] = tt.y;
            toks[i][2] = tt.z; toks[i][3] = tt.w;
        }
        float s = 0.f;
        if (use_p) {
            #pragma unroll
            for (int t = 0; t < 4; t++)
                if (toks[i][t]) s += __ldg(&pb[toks[i][t]]);
        }
        sc[i] = s;
    }

    float prob[4];
    if (use_p) {
        float mx = fmaxf(fmaxf(sc[0], sc[1]), fmaxf(sc[2], sc[3]));
        #pragma unroll
        for (int o = 16; o; o >>= 1) mx = fmaxf(mx, __shfl_xor_sync(0xffffffffu, mx, o));
        if ((tid & 31) == 0) red[tid >> 5] = mx;
        __syncthreads();
        float bm = red[0];
        #pragma unroll
        for (int i = 1; i < 16; i++) bm = fmaxf(bm, red[i]);
        float sum = 0.f;
        #pragma unroll
        for (int i = 0; i < 4; i++) { float e = __expf(sc[i] - bm); sc[i] = e; sum += e; }
        #pragma unroll
        for (int o = 16; o; o >>= 1) sum += __shfl_xor_sync(0xffffffffu, sum, o);
        __syncthreads();
        if ((tid & 31) == 0) red[tid >> 5] = sum;
        __syncthreads();
        float tot = 0.f;
        #pragma unroll
        for (int i = 0; i < 16; i++) tot += red[i];
        float inv = 1.f / tot;
        #pragma unroll
        for (int i = 0; i < 4; i++) prob[i] = sc[i] * inv;
    } else {
        #pragma unroll
        for (int i = 0; i < 4; i++) prob[i] = 1.0f / (float)MM;
    }

    #pragma unroll
    for (int i = 0; i < 4; i++) {
        #pragma unroll
        for (int t = 0; t < 4; t++)
            if (toks[i][t]) atomicAdd(&wb[toks[i][t]], prob[i]);
    }
}

// ---------------------------------------------------------------------------
// p = u @ C^T :  p[b][v] = sum_k u[b][k] * Ct[v][k]
// One full-K tile per block: 128 v x 128 k, no inner syncs.
// Cst stored transposed [k][v] with XOR swizzle: elem (k, r) at
//   k*128 + (r ^ ((k>>2 & 7) << 2)).  Store: 4-way; read: conflict-free.
// us [k][b]: staged with lanes varying b (conflict-free STS).
// ---------------------------------------------------------------------------
__global__ __launch_bounds__(256, 2) void p_gemm(const float* __restrict__ Ct,
                                                 const float* __restrict__ u) {
    extern __shared__ float sm[];
    float* Cst = sm;                  // [128][128] swizzled
    float* us  = sm + 128 * 128;      // [128][64]

    int tid = threadIdx.x;
    int vlane = tid & 31;
    int bg = tid >> 5;
    int vbase = blockIdx.x * 128;

    // stage Cst: coalesced LDG.128; transposed scalar STS, swizzled (4-way max)
    #pragma unroll
    for (int q = 0; q < 16; q++) {
        int fi = tid + q * 256;
        int r = fi >> 5;          // v in tile (constant per warp)
        int c4 = fi & 31;         // float4 index along k (lane)
        int v = vbase + r;
        float4 f = make_float4(0.f, 0.f, 0.f, 0.f);
        if (v < VV) f = *(const float4*)(Ct + (size_t)v * DD + c4 * 4);
        int rs = r ^ ((c4 & 7) << 2);   // swizzled row slot for k = 4*c4..+3
        Cst[(c4 * 4 + 0) * 128 + rs] = f.x;
        Cst[(c4 * 4 + 1) * 128 + rs] = f.y;
        Cst[(c4 * 4 + 2) * 128 + rs] = f.z;
        Cst[(c4 * 4 + 3) * 128 + rs] = f.w;
    }
    // stage us[k][b]: lanes vary b -> conflict-free STS (u strided LDG, L2-hot)
    #pragma unroll
    for (int q = 0; q < 8; q++) {
        int fi = tid + q * 256;
        int b_ = fi & 63;
        int k4 = fi >> 6;         // 0..31
        float4 f = *(const float4*)(u + b_ * DD + k4 * 4);
        us[(k4 * 4 + 0) * 64 + b_] = f.x;
        us[(k4 * 4 + 1) * 64 + b_] = f.y;
        us[(k4 * 4 + 2) * 64 + b_] = f.z;
        us[(k4 * 4 + 3) * 64 + b_] = f.w;
    }
    __syncthreads();

    ull acc[4][4];   // [j: v in float4][pp: b-pair]
    #pragma unroll
    for (int j = 0; j < 4; j++)
        #pragma unroll
        for (int pp = 0; pp < 4; pp++) acc[j][pp] = pack2(0.f, 0.f);

    #pragma unroll 4
    for (int k = 0; k < 128; k++) {
        int sw = ((k >> 2) & 7) << 2;   // hoisted per 4-k group after unroll
        float4 c = *(const float4*)&Cst[k * 128 + ((vlane * 4) ^ sw)];
        // 8 b's via two broadcast LDS.128
        ulonglong2 ua = *(const ulonglong2*)&us[k * 64 + bg * 8];
        ulonglong2 ub = *(const ulonglong2*)&us[k * 64 + bg * 8 + 4];
        ull up[4];
        up[0] = ua.x; up[1] = ua.y; up[2] = ub.x; up[3] = ub.y;
        ull c2[4];
        c2[0] = pack2(c.x, c.x); c2[1] = pack2(c.y, c.y);
        c2[2] = pack2(c.z, c.z); c2[3] = pack2(c.w, c.w);
        #pragma unroll
        for (int j = 0; j < 4; j++)
            #pragma unroll
            for (int pp = 0; pp < 4; pp++)
                acc[j][pp] = fma2(up[pp], c2[j], acc[j][pp]);
    }

    // output: per (b, pair-half) assemble float4 over 4 adjacent v -> STG.128
    int v0 = vbase + vlane * 4;
    if (v0 < VV) {
        #pragma unroll
        for (int pp = 0; pp < 4; pp++) {
            int b0 = bg * 8 + pp * 2;
            float2 e0 = unpack2(acc[0][pp]);
            float2 e1 = unpack2(acc[1][pp]);
            float2 e2 = unpack2(acc[2][pp]);
            float2 e3 = unpack2(acc[3][pp]);
            float4 f0 = make_float4(e0.x, e1.x, e2.x, e3.x);
            float4 f1 = make_float4(e0.y, e1.y, e2.y, e3.y);
            *(float4*)&g_p[(size_t)b0 * VV + v0]       = f0;
            *(float4*)&g_p[(size_t)(b0 + 1) * VV + v0] = f1;
        }
    }
}

// ---------------------------------------------------------------------------
// u += w @ C :  u[b][d] += sum_v w[b][v] * Ct[v][d]   (RED.F32 into u)
// Grid 261 blocks x 6 tiles of 32 v, register-double-buffered staging.
// ---------------------------------------------------------------------------
__global__ __launch_bounds__(256, 2) void o_gemm(const float* __restrict__ Ct,
                                                 float* __restrict__ u,
                                                 int do_zero) {
    __shared__ float Cs[32][128];     // [v][d]
    __shared__ float ws[32][64];      // [v][b] plain

    int tid = threadIdx.x;
    int dlane = tid & 31;
    int bg = tid >> 5;
    int vstart = blockIdx.x * (OG_TILES * 32);

    int sr  = tid >> 5, sc4 = tid & 31;        // Cs: 4 float4/thread (q rows +8)
    int sv4 = tid >> 6, sb = tid & 63;         // ws: 2 float4/thread (q v4 +4)

    float4 rc[4], rw[2];

    // prefetch tile 0
    {
        int vb = vstart;
        #pragma unroll
        for (int q = 0; q < 4; q++) {
            int v = vb + sr + q * 8;
            rc[q] = make_float4(0.f, 0.f, 0.f, 0.f);
            if (v < VV) rc[q] = *(const float4*)(Ct + (size_t)v * DD + sc4 * 4);
        }
        #pragma unroll
        for (int q = 0; q < 2; q++) {
            int v = vb + (sv4 + q * 4) * 4;
            rw[q] = make_float4(0.f, 0.f, 0.f, 0.f);
            if (v < VV) rw[q] = *(const float4*)(g_w + (size_t)sb * VV + v);
        }
    }

    ull acc[4][4];   // [bp: b-pair][j: d]
    #pragma unroll
    for (int bp = 0; bp < 4; bp++)
        #pragma unroll
        for (int j = 0; j < 4; j++) acc[bp][j] = pack2(0.f, 0.f);

    #pragma unroll 1
    for (int t = 0; t < OG_TILES; t++) {
        __syncthreads();
        #pragma unroll
        for (int q = 0; q < 4; q++)
            *(float4*)&Cs[sr + q * 8][sc4 * 4] = rc[q];
        #pragma unroll
        for (int q = 0; q < 2; q++) {
            int vr = (sv4 + q * 4) * 4;
            ws[vr + 0][sb] = rw[q].x;
            ws[vr + 1][sb] = rw[q].y;
            ws[vr + 2][sb] = rw[q].z;
            ws[vr + 3][sb] = rw[q].w;
        }
        __syncthreads();

        if (t + 1 < OG_TILES) {
            int vb = vstart + (t + 1) * 32;
            #pragma unroll
            for (int q = 0; q < 4; q++) {
                int v = vb + sr + q * 8;
                rc[q] = make_float4(0.f, 0.f, 0.f, 0.f);
                if (v < VV) rc[q] = *(const float4*)(Ct + (size_t)v * DD + sc4 * 4);
            }
            #pragma unroll
            for (int q = 0; q < 2; q++) {
                int v = vb + (sv4 + q * 4) * 4;
                rw[q] = make_float4(0.f, 0.f, 0.f, 0.f);
                if (v < VV) rw[q] = *(const float4*)(g_w + (size_t)sb * VV + v);
            }
        }

        #pragma unroll 4
        for (int v = 0; v < 32; v++) {
            ulonglong2 wa = *(const ulonglong2*)&ws[v][bg * 8];       // broadcast
            ulonglong2 wb2 = *(const ulonglong2*)&ws[v][bg * 8 + 4];  // broadcast
            float4 c = *(const float4*)&Cs[v][dlane * 4];
            ull wp[4];
            wp[0] = wa.x; wp[1] = wa.y; wp[2] = wb2.x; wp[3] = wb2.y;
            ull c2[4];
            c2[0] = pack2(c.x, c.x); c2[1] = pack2(c.y, c.y);
            c2[2] = pack2(c.z, c.z); c2[3] = pack2(c.w, c.w);
            #pragma unroll
            for (int bp = 0; bp < 4; bp++)
                #pragma unroll
                for (int j = 0; j < 4; j++)
                    acc[bp][j] = fma2(wp[bp], c2[j], acc[bp][j]);
        }
    }

    // RED directly into u
    #pragma unroll
    for (int bp = 0; bp < 4; bp++) {
        int b0 = bg * 8 + bp * 2;
        #pragma unroll
        for (int j = 0; j < 4; j++) {
            float2 a = unpack2(acc[bp][j]);
            atomicAdd(&u[b0 * DD + dlane * 4 + j], a.x);
            atomicAdd(&u[(b0 + 1) * DD + dlane * 4 + j], a.y);
        }
    }

    // zero own w chunk for the next hop's scatter (chunks disjoint per block)
    if (do_zero) {
        float4 z = make_float4(0.f, 0.f, 0.f, 0.f);
        for (int idx = tid; idx < 64 * 48; idx += 256) {
            int b_ = idx / 48;
            int v = vstart + (idx % 48) * 4;
            if (v < VV)
                *(float4*)&g_w[(size_t)b_ * VV + v] = z;
        }
    }
}

// ---------------------------------------------------------------------------
extern "C" void kernel_launch(void* const* d_in, const int* in_sizes, int n_in,
                              void* d_out, int out_size) {
    int si = 0, ci = 1;
    if (n_in >= 2 && in_sizes[0] > in_sizes[1]) { si = 1; ci = 0; }
    const void* story = d_in[si];
    const float* C = (const float*)d_in[ci];
    float* u = (float*)d_out;

    static int smem_set = 0;
    const int PG_SMEM = (128 * 128 + 128 * 64) * 4;   // 98304 B
    if (!smem_set) {
        cudaFuncSetAttribute(p_gemm, cudaFuncAttributeMaxDynamicSharedMemorySize, PG_SMEM);
        smem_set = 1;
    }

    prologue<<<3127, 256>>>((const unsigned int*)story, u);

    for (int h = 0; h < 3; h++) {
        if (h) p_gemm<<<PG_GRID, 256, PG_SMEM>>>(C + (size_t)h * VV * DD, u);
        fused_attn<<<BB, 512>>>(story, h > 0 ? 1 : 0);
        o_gemm<<<OG_GRID, 256>>>(C + (size_t)(h + 1) * VV * DD, u, h < 2 ? 1 : 0);
    }
}

// round 8
// speedup vs baseline: 1.8695x; 1.2768x over previous
#include <cuda_runtime.h>
#include <cuda_bf16.h>
#include <math.h>

#define MM 2048
#define BB 64
#define TT 4
#define DD 128
#define VV 50000

#define PG_GRID 391          // ceil(50000/128)
#define OG_GRID 261          // 261*192 = 50112 >= 50000
#define OG_TILES 6

// Scratch (device globals). g_p layout: [v][b]  (v-major, 64 floats per v row)
__device__ __align__(16) float g_w[BB * VV];
__device__ __align__(16) float g_p[VV * BB];
__device__ int g_is64;

typedef unsigned long long ull;

__device__ __forceinline__ ull pack2(float x, float y) {
    ull r;
    asm("mov.b64 %0, {%1,%2};" : "=l"(r) : "f"(x), "f"(y));
    return r;
}
__device__ __forceinline__ ull fma2(ull a, ull b, ull c) {
    ull d;
    asm("fma.rn.f32x2 %0, %1, %2, %3;" : "=l"(d) : "l"(a), "l"(b), "l"(c));
    return d;
}
__device__ __forceinline__ float2 unpack2(ull a) {
    float x, y;
    asm("mov.b64 {%0,%1}, %2;" : "=f"(x), "=f"(y) : "l"(a));
    return make_float2(x, y);
}
__device__ __forceinline__ unsigned smem_u32(const void* p) {
    unsigned a;
    asm("{ .reg .u64 t; cvta.to.shared.u64 t, %1; cvt.u32.u64 %0, t; }" : "=r"(a) : "l"(p));
    return a;
}
// bf16x2 pack: lo element first in memory
__device__ __forceinline__ unsigned cvt2bf(float lo, float hi) {
    unsigned r;
    asm("cvt.rn.bf16x2.f32 %0, %1, %2;" : "=r"(r) : "f"(hi), "f"(lo));
    return r;
}
__device__ __forceinline__ void ldsm_x4(unsigned* r, unsigned addr) {
    asm volatile("ldmatrix.sync.aligned.m8n8.x4.shared.b16 {%0,%1,%2,%3}, [%4];"
                 : "=r"(r[0]), "=r"(r[1]), "=r"(r[2]), "=r"(r[3]) : "r"(addr));
}
__device__ __forceinline__ void mma16816(float* c, const unsigned* a, unsigned b0, unsigned b1) {
    asm volatile(
        "mma.sync.aligned.m16n8k16.row.col.f32.bf16.bf16.f32 "
        "{%0,%1,%2,%3}, {%4,%5,%6,%7}, {%8,%9}, {%0,%1,%2,%3};"
        : "+f"(c[0]), "+f"(c[1]), "+f"(c[2]), "+f"(c[3])
        : "r"(a[0]), "r"(a[1]), "r"(a[2]), "r"(a[3]), "r"(b0), "r"(b1));
}

// ---------------------------------------------------------------------------
// Prologue: zero g_w, zero u, dtype probe
// ---------------------------------------------------------------------------
__global__ __launch_bounds__(256) void prologue(const unsigned int* __restrict__ s,
                                                float* __restrict__ u) {
    int blk = blockIdx.x;
    int tid = threadIdx.x;
    if (blk < 3125) {
        int i = blk * 256 + tid;
        float4 z = make_float4(0.f, 0.f, 0.f, 0.f);
        *(float4*)&g_w[(size_t)i * 4] = z;
    } else if (blk == 3125) {
        for (int i = tid; i < BB * DD; i += 256) u[i] = 0.f;
    } else if (tid < 32) {
        unsigned int acc = 0;
        #pragma unroll
        for (int i = tid; i < 256; i += 32) acc |= s[2 * i + 1];
        #pragma unroll
        for (int o = 16; o; o >>= 1) acc |= __shfl_xor_sync(0xffffffffu, acc, o);
        if (tid == 0) g_is64 = (acc == 0) ? 1 : 0;
    }
}

// ---------------------------------------------------------------------------
// Fused attention. g_p is [v][b]: score gather at g_p[tok*BB + b].
// ---------------------------------------------------------------------------
__global__ __launch_bounds__(512) void fused_attn(const void* __restrict__ story,
                                                  int use_p) {
    int b = blockIdx.x;
    int tid = threadIdx.x;
    __shared__ float red[16];

    float* wb = g_w + (size_t)b * VV;
    int is64 = g_is64;
    int toks[4][4];
    float sc[4];

    #pragma unroll
    for (int i = 0; i < 4; i++) {
        int m = tid + i * 512;
        if (is64) {
            const long long* sp = (const long long*)story + (size_t)m * (BB * TT) + b * TT;
            longlong2 t0 = ((const longlong2*)sp)[0];
            longlong2 t1 = ((const longlong2*)sp)[1];
            toks[i][0] = (int)t0.x; toks[i][1] = (int)t0.y;
            toks[i][2] = (int)t1.x; toks[i][3] = (int)t1.y;
        } else {
            int4 tt = *((const int4*)((const int*)story + (size_t)m * (BB * TT) + b * TT));
            toks[i][0] = tt.x; toks[i][1] = tt.y;
            toks[i][2] = tt.z; toks[i][3] = tt.w;
        }
        float s = 0.f;
        if (use_p) {
            #pragma unroll
            for (int t = 0; t < 4; t++)
                if (toks[i][t]) s += __ldg(&g_p[(size_t)toks[i][t] * BB + b]);
        }
        sc[i] = s;
    }

    float prob[4];
    if (use_p) {
        float mx = fmaxf(fmaxf(sc[0], sc[1]), fmaxf(sc[2], sc[3]));
        #pragma unroll
        for (int o = 16; o; o >>= 1) mx = fmaxf(mx, __shfl_xor_sync(0xffffffffu, mx, o));
        if ((tid & 31) == 0) red[tid >> 5] = mx;
        __syncthreads();
        float bm = red[0];
        #pragma unroll
        for (int i = 1; i < 16; i++) bm = fmaxf(bm, red[i]);
        float sum = 0.f;
        #pragma unroll
        for (int i = 0; i < 4; i++) { float e = __expf(sc[i] - bm); sc[i] = e; sum += e; }
        #pragma unroll
        for (int o = 16; o; o >>= 1) sum += __shfl_xor_sync(0xffffffffu, sum, o);
        __syncthreads();
        if ((tid & 31) == 0) red[tid >> 5] = sum;
        __syncthreads();
        float tot = 0.f;
        #pragma unroll
        for (int i = 0; i < 16; i++) tot += red[i];
        float inv = 1.f / tot;
        #pragma unroll
        for (int i = 0; i < 4; i++) prob[i] = sc[i] * inv;
    } else {
        #pragma unroll
        for (int i = 0; i < 4; i++) prob[i] = 1.0f / (float)MM;
    }

    #pragma unroll
    for (int i = 0; i < 4; i++) {
        #pragma unroll
        for (int t = 0; t < 4; t++)
            if (toks[i][t]) atomicAdd(&wb[toks[i][t]], prob[i]);
    }
}

// ---------------------------------------------------------------------------
// p_gemm_mma: p[v][b] = sum_k Ct[v][k] * u[b][k], bf16 3-term split via
// mma.sync.m16n8k16 (row.col). A = C tile [128v x 128k] hi/lo bf16;
// B = u [64b x 128k] hi/lo bf16 (n-major x k -> non-trans ldmatrix = .col frag).
// smem rows: 128 bf16 = 256B, XOR swizzle chunk16 ^= (row & 7).
// 8 warps: warp w -> v rows [16w, 16w+16). Per kstep: 2 A-ldsm + 4 B-ldsm + 24 mma.
// ---------------------------------------------------------------------------
__global__ __launch_bounds__(256, 2) void p_gemm_mma(const float* __restrict__ Ct,
                                                     const float* __restrict__ u) {
    extern __shared__ char dsm[];
    unsigned sbase = smem_u32(dsm);
    const unsigned A_HI = 0, A_LO = 32768, B_HI = 65536, B_LO = 81920;

    int tid = threadIdx.x;
    int wid = tid >> 5;
    int lane = tid & 31;
    int vbase = blockIdx.x * 128;

    // ---- stage A: 128 rows x 16 chunk16 (each chunk = 8 floats -> 16B bf16) ----
    #pragma unroll
    for (int q = 0; q < 8; q++) {
        int fi = tid + q * 256;
        int row = fi >> 4;
        int c16 = fi & 15;
        int v = vbase + row;
        float4 f0 = make_float4(0.f, 0.f, 0.f, 0.f), f1 = f0;
        if (v < VV) {
            const float* src = Ct + (size_t)v * DD + c16 * 8;
            f0 = *(const float4*)src;
            f1 = *(const float4*)(src + 4);
        }
        uint4 hi, lo;
        hi.x = cvt2bf(f0.x, f0.y); hi.y = cvt2bf(f0.z, f0.w);
        hi.z = cvt2bf(f1.x, f1.y); hi.w = cvt2bf(f1.z, f1.w);
        float hx, hy, hz, hw;
        hx = __bfloat162float(__float2bfloat16(f0.x));
        hy = __bfloat162float(__float2bfloat16(f0.y));
        hz = __bfloat162float(__float2bfloat16(f0.z));
        hw = __bfloat162float(__float2bfloat16(f0.w));
        lo.x = cvt2bf(f0.x - hx, f0.y - hy); lo.y = cvt2bf(f0.z - hz, f0.w - hw);
        hx = __bfloat162float(__float2bfloat16(f1.x));
        hy = __bfloat162float(__float2bfloat16(f1.y));
        hz = __bfloat162float(__float2bfloat16(f1.z));
        hw = __bfloat162float(__float2bfloat16(f1.w));
        lo.z = cvt2bf(f1.x - hx, f1.y - hy); lo.w = cvt2bf(f1.z - hz, f1.w - hw);
        unsigned off = (unsigned)(row * 256 + ((c16 ^ (row & 7)) << 4));
        *(uint4*)(dsm + A_HI + off) = hi;
        *(uint4*)(dsm + A_LO + off) = lo;
    }
    // ---- stage B: 64 rows (b) x 16 chunk16 ----
    #pragma unroll
    for (int q = 0; q < 4; q++) {
        int fi = tid + q * 256;
        int row = fi >> 4;      // b
        int c16 = fi & 15;
        const float* src = u + row * DD + c16 * 8;
        float4 f0 = *(const float4*)src;
        float4 f1 = *(const float4*)(src + 4);
        uint4 hi, lo;
        hi.x = cvt2bf(f0.x, f0.y); hi.y = cvt2bf(f0.z, f0.w);
        hi.z = cvt2bf(f1.x, f1.y); hi.w = cvt2bf(f1.z, f1.w);
        float hx, hy, hz, hw;
        hx = __bfloat162float(__float2bfloat16(f0.x));
        hy = __bfloat162float(__float2bfloat16(f0.y));
        hz = __bfloat162float(__float2bfloat16(f0.z));
        hw = __bfloat162float(__float2bfloat16(f0.w));
        lo.x = cvt2bf(f0.x - hx, f0.y - hy); lo.y = cvt2bf(f0.z - hz, f0.w - hw);
        hx = __bfloat162float(__float2bfloat16(f1.x));
        hy = __bfloat162float(__float2bfloat16(f1.y));
        hz = __bfloat162float(__float2bfloat16(f1.z));
        hw = __bfloat162float(__float2bfloat16(f1.w));
        lo.z = cvt2bf(f1.x - hx, f1.y - hy); lo.w = cvt2bf(f1.z - hz, f1.w - hw);
        unsigned off = (unsigned)(row * 256 + ((c16 ^ (row & 7)) << 4));
        *(uint4*)(dsm + B_HI + off) = hi;
        *(uint4*)(dsm + B_LO + off) = lo;
    }
    __syncthreads();

    // ---- ldmatrix lane address bases ----
    // A (x4): matrices: (rows M0+0-7, k0-7), (M0+8-15, k0-7), (M0+0-7, k8-15), (M0+8-15, k8-15)
    int mi = lane >> 3, r8 = lane & 7;
    int rowA = wid * 16 + (mi & 1) * 8 + r8;
    int kselA = mi >> 1;                 // 0 or 1 -> col16 += ksel
    unsigned baseA = sbase + (unsigned)rowA * 256;
    int sA = rowA & 7;
    // B (x4) for atom pair pa: rows pa*16 + (lane>>4)*8 + r8; colsel = (lane>>3)&1
    int rowB_off = ((lane >> 4) & 1) * 8 + r8;
    int kselB = (lane >> 3) & 1;

    float acc[8][4];
    #pragma unroll
    for (int na = 0; na < 8; na++)
        #pragma unroll
        for (int j = 0; j < 4; j++) acc[na][j] = 0.f;

    #pragma unroll
    for (int ks = 0; ks < 8; ks++) {
        unsigned a_hi[4], a_lo[4];
        unsigned cA = (unsigned)(((2 * ks + kselA) ^ sA) << 4);
        ldsm_x4(a_hi, baseA + A_HI + cA);
        ldsm_x4(a_lo, baseA + A_LO + cA);
        #pragma unroll
        for (int pa = 0; pa < 4; pa++) {
            int rowB = pa * 16 + rowB_off;
            unsigned baseB = sbase + (unsigned)rowB * 256;
            unsigned cB = (unsigned)(((2 * ks + kselB) ^ (rowB & 7)) << 4);
            unsigned bh[4], bl[4];
            ldsm_x4(bh, baseB + B_HI + cB);
            ldsm_x4(bl, baseB + B_LO + cB);
            mma16816(acc[2 * pa],     a_hi, bh[0], bh[1]);
            mma16816(acc[2 * pa],     a_hi, bl[0], bl[1]);
            mma16816(acc[2 * pa],     a_lo, bh[0], bh[1]);
            mma16816(acc[2 * pa + 1], a_hi, bh[2], bh[3]);
            mma16816(acc[2 * pa + 1], a_hi, bl[2], bl[3]);
            mma16816(acc[2 * pa + 1], a_lo, bh[2], bh[3]);
        }
    }

    // ---- epilogue: D frag (v, b) -> g_p[v*64 + b], float2 stores ----
    int v0 = vbase + wid * 16 + (lane >> 2);
    int bq = (lane & 3) * 2;
    #pragma unroll
    for (int na = 0; na < 8; na++) {
        int b0 = na * 8 + bq;
        if (v0 < VV)
            *(float2*)&g_p[(size_t)v0 * BB + b0] = make_float2(acc[na][0], acc[na][1]);
        if (v0 + 8 < VV)
            *(float2*)&g_p[(size_t)(v0 + 8) * BB + b0] = make_float2(acc[na][2], acc[na][3]);
    }
}

// ---------------------------------------------------------------------------
// u += w @ C (RED.F32 into u); unchanged from best-known.
// ---------------------------------------------------------------------------
__global__ __launch_bounds__(256, 2) void o_gemm(const float* __restrict__ Ct,
                                                 float* __restrict__ u,
                                                 int do_zero) {
    __shared__ float Cs[32][128];
    __shared__ float ws[32][64];

    int tid = threadIdx.x;
    int dlane = tid & 31;
    int bg = tid >> 5;
    int vstart = blockIdx.x * (OG_TILES * 32);

    int sr  = tid >> 5, sc4 = tid & 31;
    int sv4 = tid >> 6, sb = tid & 63;

    float4 rc[4], rw[2];

    {
        int vb = vstart;
        #pragma unroll
        for (int q = 0; q < 4; q++) {
            int v = vb + sr + q * 8;
            rc[q] = make_float4(0.f, 0.f, 0.f, 0.f);
            if (v < VV) rc[q] = *(const float4*)(Ct + (size_t)v * DD + sc4 * 4);
        }
        #pragma unroll
        for (int q = 0; q < 2; q++) {
            int v = vb + (sv4 + q * 4) * 4;
            rw[q] = make_float4(0.f, 0.f, 0.f, 0.f);
            if (v < VV) rw[q] = *(const float4*)(g_w + (size_t)sb * VV + v);
        }
    }

    ull acc[4][4];
    #pragma unroll
    for (int bp = 0; bp < 4; bp++)
        #pragma unroll
        for (int j = 0; j < 4; j++) acc[bp][j] = pack2(0.f, 0.f);

    #pragma unroll 1
    for (int t = 0; t < OG_TILES; t++) {
        __syncthreads();
        #pragma unroll
        for (int q = 0; q < 4; q++)
            *(float4*)&Cs[sr + q * 8][sc4 * 4] = rc[q];
        #pragma unroll
        for (int q = 0; q < 2; q++) {
            int vr = (sv4 + q * 4) * 4;
            ws[vr + 0][sb] = rw[q].x;
            ws[vr + 1][sb] = rw[q].y;
            ws[vr + 2][sb] = rw[q].z;
            ws[vr + 3][sb] = rw[q].w;
        }
        __syncthreads();

        if (t + 1 < OG_TILES) {
            int vb = vstart + (t + 1) * 32;
            #pragma unroll
            for (int q = 0; q < 4; q++) {
                int v = vb + sr + q * 8;
                rc[q] = make_float4(0.f, 0.f, 0.f, 0.f);
                if (v < VV) rc[q] = *(const float4*)(Ct + (size_t)v * DD + sc4 * 4);
            }
            #pragma unroll
            for (int q = 0; q < 2; q++) {
                int v = vb + (sv4 + q * 4) * 4;
                rw[q] = make_float4(0.f, 0.f, 0.f, 0.f);
                if (v < VV) rw[q] = *(const float4*)(g_w + (size_t)sb * VV + v);
            }
        }

        #pragma unroll 4
        for (int v = 0; v < 32; v++) {
            ulonglong2 wa = *(const ulonglong2*)&ws[v][bg * 8];
            ulonglong2 wb2 = *(const ulonglong2*)&ws[v][bg * 8 + 4];
            float4 c = *(const float4*)&Cs[v][dlane * 4];
            ull wp[4];
            wp[0] = wa.x; wp[1] = wa.y; wp[2] = wb2.x; wp[3] = wb2.y;
            ull c2[4];
            c2[0] = pack2(c.x, c.x); c2[1] = pack2(c.y, c.y);
            c2[2] = pack2(c.z, c.z); c2[3] = pack2(c.w, c.w);
            #pragma unroll
            for (int bp = 0; bp < 4; bp++)
                #pragma unroll
                for (int j = 0; j < 4; j++)
                    acc[bp][j] = fma2(wp[bp], c2[j], acc[bp][j]);
        }
    }

    #pragma unroll
    for (int bp = 0; bp < 4; bp++) {
        int b0 = bg * 8 + bp * 2;
        #pragma unroll
        for (int j = 0; j < 4; j++) {
            float2 a = unpack2(acc[bp][j]);
            atomicAdd(&u[b0 * DD + dlane * 4 + j], a.x);
            atomicAdd(&u[(b0 + 1) * DD + dlane * 4 + j], a.y);
        }
    }

    if (do_zero) {
        float4 z = make_float4(0.f, 0.f, 0.f, 0.f);
        for (int idx = tid; idx < 64 * 48; idx += 256) {
            int b_ = idx / 48;
            int v = vstart + (idx % 48) * 4;
            if (v < VV)
                *(float4*)&g_w[(size_t)b_ * VV + v] = z;
        }
    }
}

// ---------------------------------------------------------------------------
extern "C" void kernel_launch(void* const* d_in, const int* in_sizes, int n_in,
                              void* d_out, int out_size) {
    int si = 0, ci = 1;
    if (n_in >= 2 && in_sizes[0] > in_sizes[1]) { si = 1; ci = 0; }
    const void* story = d_in[si];
    const float* C = (const float*)d_in[ci];
    float* u = (float*)d_out;

    const int PG_SMEM = 98304;   // A hi/lo 32K*2 + B hi/lo 16K*2
    static int smem_set = 0;
    if (!smem_set) {
        cudaFuncSetAttribute(p_gemm_mma, cudaFuncAttributeMaxDynamicSharedMemorySize, PG_SMEM);
        smem_set = 1;
    }

    prologue<<<3127, 256>>>((const unsigned int*)story, u);

    for (int h = 0; h < 3; h++) {
        if (h) p_gemm_mma<<<PG_GRID, 256, PG_SMEM>>>(C + (size_t)h * VV * DD, u);
        fused_attn<<<BB, 512>>>(story, h > 0 ? 1 : 0);
        o_gemm<<<OG_GRID, 256>>>(C + (size_t)(h + 1) * VV * DD, u, h < 2 ? 1 : 0);
    }
}

// round 9
// speedup vs baseline: 2.3016x; 1.2311x over previous
#include <cuda_runtime.h>
#include <cuda_bf16.h>
#include <math.h>

#define MM 2048
#define BB 64
#define TT 4
#define DD 128
#define VV 50000

#define PG_GRID 391          // ceil(50000/128)
#define OG_GRID 261          // 261*192 = 50112 >= 50000
#define OG_TILES 6

// Scratch (device globals). g_p layout: [v][b]  (v-major, 64 floats per v row)
__device__ __align__(16) float g_w[BB * VV];
__device__ __align__(16) float g_p[VV * BB];
__device__ int g_is64;

typedef unsigned long long ull;

__device__ __forceinline__ unsigned smem_u32(const void* p) {
    unsigned a;
    asm("{ .reg .u64 t; cvta.to.shared.u64 t, %1; cvt.u32.u64 %0, t; }" : "=r"(a) : "l"(p));
    return a;
}
// bf16x2 pack: lo element first in memory
__device__ __forceinline__ unsigned cvt2bf(float lo, float hi) {
    unsigned r;
    asm("cvt.rn.bf16x2.f32 %0, %1, %2;" : "=r"(r) : "f"(hi), "f"(lo));
    return r;
}
__device__ __forceinline__ void ldsm_x4(unsigned* r, unsigned addr) {
    asm volatile("ldmatrix.sync.aligned.m8n8.x4.shared.b16 {%0,%1,%2,%3}, [%4];"
                 : "=r"(r[0]), "=r"(r[1]), "=r"(r[2]), "=r"(r[3]) : "r"(addr));
}
__device__ __forceinline__ void ldsm_x4_t(unsigned* r, unsigned addr) {
    asm volatile("ldmatrix.sync.aligned.m8n8.x4.trans.shared.b16 {%0,%1,%2,%3}, [%4];"
                 : "=r"(r[0]), "=r"(r[1]), "=r"(r[2]), "=r"(r[3]) : "r"(addr));
}
__device__ __forceinline__ void mma16816(float* c, const unsigned* a, unsigned b0, unsigned b1) {
    asm volatile(
        "mma.sync.aligned.m16n8k16.row.col.f32.bf16.bf16.f32 "
        "{%0,%1,%2,%3}, {%4,%5,%6,%7}, {%8,%9}, {%0,%1,%2,%3};"
        : "+f"(c[0]), "+f"(c[1]), "+f"(c[2]), "+f"(c[3])
        : "r"(a[0]), "r"(a[1]), "r"(a[2]), "r"(a[3]), "r"(b0), "r"(b1));
}

// ---------------------------------------------------------------------------
// Prologue: zero g_w, zero u, dtype probe
// ---------------------------------------------------------------------------
__global__ __launch_bounds__(256) void prologue(const unsigned int* __restrict__ s,
                                                float* __restrict__ u) {
    int blk = blockIdx.x;
    int tid = threadIdx.x;
    if (blk < 3125) {
        int i = blk * 256 + tid;
        float4 z = make_float4(0.f, 0.f, 0.f, 0.f);
        *(float4*)&g_w[(size_t)i * 4] = z;
    } else if (blk == 3125) {
        for (int i = tid; i < BB * DD; i += 256) u[i] = 0.f;
    } else if (tid < 32) {
        unsigned int acc = 0;
        #pragma unroll
        for (int i = tid; i < 256; i += 32) acc |= s[2 * i + 1];
        #pragma unroll
        for (int o = 16; o; o >>= 1) acc |= __shfl_xor_sync(0xffffffffu, acc, o);
        if (tid == 0) g_is64 = (acc == 0) ? 1 : 0;
    }
}

// ---------------------------------------------------------------------------
// Fused attention. g_p is [v][b]: score gather at g_p[tok*BB + b].
// ---------------------------------------------------------------------------
__global__ __launch_bounds__(512) void fused_attn(const void* __restrict__ story,
                                                  int use_p) {
    int b = blockIdx.x;
    int tid = threadIdx.x;
    __shared__ float red[16];

    float* wb = g_w + (size_t)b * VV;
    int is64 = g_is64;
    int toks[4][4];
    float sc[4];

    #pragma unroll
    for (int i = 0; i < 4; i++) {
        int m = tid + i * 512;
        if (is64) {
            const long long* sp = (const long long*)story + (size_t)m * (BB * TT) + b * TT;
            longlong2 t0 = ((const longlong2*)sp)[0];
            longlong2 t1 = ((const longlong2*)sp)[1];
            toks[i][0] = (int)t0.x; toks[i][1] = (int)t0.y;
            toks[i][2] = (int)t1.x; toks[i][3] = (int)t1.y;
        } else {
            int4 tt = *((const int4*)((const int*)story + (size_t)m * (BB * TT) + b * TT));
            toks[i][0] = tt.x; toks[i][1] = tt.y;
            toks[i][2] = tt.z; toks[i][3] = tt.w;
        }
        float s = 0.f;
        if (use_p) {
            #pragma unroll
            for (int t = 0; t < 4; t++)
                if (toks[i][t]) s += __ldg(&g_p[(size_t)toks[i][t] * BB + b]);
        }
        sc[i] = s;
    }

    float prob[4];
    if (use_p) {
        float mx = fmaxf(fmaxf(sc[0], sc[1]), fmaxf(sc[2], sc[3]));
        #pragma unroll
        for (int o = 16; o; o >>= 1) mx = fmaxf(mx, __shfl_xor_sync(0xffffffffu, mx, o));
        if ((tid & 31) == 0) red[tid >> 5] = mx;
        __syncthreads();
        float bm = red[0];
        #pragma unroll
        for (int i = 1; i < 16; i++) bm = fmaxf(bm, red[i]);
        float sum = 0.f;
        #pragma unroll
        for (int i = 0; i < 4; i++) { float e = __expf(sc[i] - bm); sc[i] = e; sum += e; }
        #pragma unroll
        for (int o = 16; o; o >>= 1) sum += __shfl_xor_sync(0xffffffffu, sum, o);
        __syncthreads();
        if ((tid & 31) == 0) red[tid >> 5] = sum;
        __syncthreads();
        float tot = 0.f;
        #pragma unroll
        for (int i = 0; i < 16; i++) tot += red[i];
        float inv = 1.f / tot;
        #pragma unroll
        for (int i = 0; i < 4; i++) prob[i] = sc[i] * inv;
    } else {
        #pragma unroll
        for (int i = 0; i < 4; i++) prob[i] = 1.0f / (float)MM;
    }

    #pragma unroll
    for (int i = 0; i < 4; i++) {
        #pragma unroll
        for (int t = 0; t < 4; t++)
            if (toks[i][t]) atomicAdd(&wb[toks[i][t]], prob[i]);
    }
}

// ---------------------------------------------------------------------------
// p_gemm_mma: p[v][b] = sum_k Ct[v][k] * u[b][k]  (unchanged, verified)
// ---------------------------------------------------------------------------
__global__ __launch_bounds__(256, 2) void p_gemm_mma(const float* __restrict__ Ct,
                                                     const float* __restrict__ u) {
    extern __shared__ char dsm[];
    unsigned sbase = smem_u32(dsm);
    const unsigned A_HI = 0, A_LO = 32768, B_HI = 65536, B_LO = 81920;

    int tid = threadIdx.x;
    int wid = tid >> 5;
    int lane = tid & 31;
    int vbase = blockIdx.x * 128;

    #pragma unroll
    for (int q = 0; q < 8; q++) {
        int fi = tid + q * 256;
        int row = fi >> 4;
        int c16 = fi & 15;
        int v = vbase + row;
        float4 f0 = make_float4(0.f, 0.f, 0.f, 0.f), f1 = f0;
        if (v < VV) {
            const float* src = Ct + (size_t)v * DD + c16 * 8;
            f0 = *(const float4*)src;
            f1 = *(const float4*)(src + 4);
        }
        uint4 hi, lo;
        hi.x = cvt2bf(f0.x, f0.y); hi.y = cvt2bf(f0.z, f0.w);
        hi.z = cvt2bf(f1.x, f1.y); hi.w = cvt2bf(f1.z, f1.w);
        float hx, hy, hz, hw;
        hx = __bfloat162float(__float2bfloat16(f0.x));
        hy = __bfloat162float(__float2bfloat16(f0.y));
        hz = __bfloat162float(__float2bfloat16(f0.z));
        hw = __bfloat162float(__float2bfloat16(f0.w));
        lo.x = cvt2bf(f0.x - hx, f0.y - hy); lo.y = cvt2bf(f0.z - hz, f0.w - hw);
        hx = __bfloat162float(__float2bfloat16(f1.x));
        hy = __bfloat162float(__float2bfloat16(f1.y));
        hz = __bfloat162float(__float2bfloat16(f1.z));
        hw = __bfloat162float(__float2bfloat16(f1.w));
        lo.z = cvt2bf(f1.x - hx, f1.y - hy); lo.w = cvt2bf(f1.z - hz, f1.w - hw);
        unsigned off = (unsigned)(row * 256 + ((c16 ^ (row & 7)) << 4));
        *(uint4*)(dsm + A_HI + off) = hi;
        *(uint4*)(dsm + A_LO + off) = lo;
    }
    #pragma unroll
    for (int q = 0; q < 4; q++) {
        int fi = tid + q * 256;
        int row = fi >> 4;
        int c16 = fi & 15;
        const float* src = u + row * DD + c16 * 8;
        float4 f0 = *(const float4*)src;
        float4 f1 = *(const float4*)(src + 4);
        uint4 hi, lo;
        hi.x = cvt2bf(f0.x, f0.y); hi.y = cvt2bf(f0.z, f0.w);
        hi.z = cvt2bf(f1.x, f1.y); hi.w = cvt2bf(f1.z, f1.w);
        float hx, hy, hz, hw;
        hx = __bfloat162float(__float2bfloat16(f0.x));
        hy = __bfloat162float(__float2bfloat16(f0.y));
        hz = __bfloat162float(__float2bfloat16(f0.z));
        hw = __bfloat162float(__float2bfloat16(f0.w));
        lo.x = cvt2bf(f0.x - hx, f0.y - hy); lo.y = cvt2bf(f0.z - hz, f0.w - hw);
        hx = __bfloat162float(__float2bfloat16(f1.x));
        hy = __bfloat162float(__float2bfloat16(f1.y));
        hz = __bfloat162float(__float2bfloat16(f1.z));
        hw = __bfloat162float(__float2bfloat16(f1.w));
        lo.z = cvt2bf(f1.x - hx, f1.y - hy); lo.w = cvt2bf(f1.z - hz, f1.w - hw);
        unsigned off = (unsigned)(row * 256 + ((c16 ^ (row & 7)) << 4));
        *(uint4*)(dsm + B_HI + off) = hi;
        *(uint4*)(dsm + B_LO + off) = lo;
    }
    __syncthreads();

    int mi = lane >> 3, r8 = lane & 7;
    int rowA = wid * 16 + (mi & 1) * 8 + r8;
    int kselA = mi >> 1;
    unsigned baseA = sbase + (unsigned)rowA * 256;
    int sA = rowA & 7;
    int rowB_off = ((lane >> 4) & 1) * 8 + r8;
    int kselB = (lane >> 3) & 1;

    float acc[8][4];
    #pragma unroll
    for (int na = 0; na < 8; na++)
        #pragma unroll
        for (int j = 0; j < 4; j++) acc[na][j] = 0.f;

    #pragma unroll
    for (int ks = 0; ks < 8; ks++) {
        unsigned a_hi[4], a_lo[4];
        unsigned cA = (unsigned)(((2 * ks + kselA) ^ sA) << 4);
        ldsm_x4(a_hi, baseA + A_HI + cA);
        ldsm_x4(a_lo, baseA + A_LO + cA);
        #pragma unroll
        for (int pa = 0; pa < 4; pa++) {
            int rowB = pa * 16 + rowB_off;
            unsigned baseB = sbase + (unsigned)rowB * 256;
            unsigned cB = (unsigned)(((2 * ks + kselB) ^ (rowB & 7)) << 4);
            unsigned bh[4], bl[4];
            ldsm_x4(bh, baseB + B_HI + cB);
            ldsm_x4(bl, baseB + B_LO + cB);
            mma16816(acc[2 * pa],     a_hi, bh[0], bh[1]);
            mma16816(acc[2 * pa],     a_hi, bl[0], bl[1]);
            mma16816(acc[2 * pa],     a_lo, bh[0], bh[1]);
            mma16816(acc[2 * pa + 1], a_hi, bh[2], bh[3]);
            mma16816(acc[2 * pa + 1], a_hi, bl[2], bl[3]);
            mma16816(acc[2 * pa + 1], a_lo, bh[2], bh[3]);
        }
    }

    int v0 = vbase + wid * 16 + (lane >> 2);
    int bq = (lane & 3) * 2;
    #pragma unroll
    for (int na = 0; na < 8; na++) {
        int b0 = na * 8 + bq;
        if (v0 < VV)
            *(float2*)&g_p[(size_t)v0 * BB + b0] = make_float2(acc[na][0], acc[na][1]);
        if (v0 + 8 < VV)
            *(float2*)&g_p[(size_t)(v0 + 8) * BB + b0] = make_float2(acc[na][2], acc[na][3]);
    }
}

// ---------------------------------------------------------------------------
// o_gemm_mma: u[b][d] += sum_v w[b][v] * Ct[v][d]  via mma.sync, 3-term split.
// A = w staged [v][b] (k-major, trans ldsm), B = C staged [v][d] (trans ldsm).
// Warp grid 4m x 2n: warp = m16 (b) x n64 (d). 6 tiles of 32 v, reg prefetch.
// smem: C hi/lo 8K+8K (rows 256B), w hi/lo 4K+4K (rows 128B), XOR swizzled.
// ---------------------------------------------------------------------------
__global__ __launch_bounds__(256) void o_gemm_mma(const float* __restrict__ Ct,
                                                  float* __restrict__ u,
                                                  int do_zero) {
    __shared__ __align__(16) char osm[24576];
    const unsigned C_HI = 0, C_LO = 8192, W_HI = 16384, W_LO = 20480;
    unsigned sbase = smem_u32(osm);

    int tid = threadIdx.x;
    int wid = tid >> 5;
    int lane = tid & 31;
    int mw = wid & 3;        // m-warp: b rows [mw*16, +16)
    int nw = wid >> 2;       // n-warp: d cols [nw*64, +64)
    int vstart = blockIdx.x * (OG_TILES * 32);

    // staging maps
    int sc_row = tid >> 5, sc4 = tid & 31;   // C: 4 float4/thread, rows +8
    int sw_b = tid >> 3, sw_v4 = tid & 7;    // w: 1 float4/thread... need 2

    float4 rc[4], rw[2];
    {
        int vb = vstart;
        #pragma unroll
        for (int q = 0; q < 4; q++) {
            int v = vb + sc_row + q * 8;
            rc[q] = make_float4(0.f, 0.f, 0.f, 0.f);
            if (v < VV) rc[q] = *(const float4*)(Ct + (size_t)v * DD + sc4 * 4);
        }
        // w: 64 b x 8 float4 = 512 float4; 2/thread: fi = tid + q*256
        #pragma unroll
        for (int q = 0; q < 2; q++) {
            int fi = tid + q * 256;
            int b_ = fi >> 3, v4 = fi & 7;
            int v = vb + v4 * 4;
            rw[q] = make_float4(0.f, 0.f, 0.f, 0.f);
            if (v < VV) rw[q] = *(const float4*)(g_w + (size_t)b_ * VV + v);
        }
    }

    float acc[8][4];
    #pragma unroll
    for (int na = 0; na < 8; na++)
        #pragma unroll
        for (int j = 0; j < 4; j++) acc[na][j] = 0.f;

    int g = lane >> 3, r8 = lane & 7;
    // A-trans: groups (k0,m0)(k0,m8)(k8,m0)(k8,m8)
    unsigned a_roff = (unsigned)(((g >> 1) * 8 + r8) * 128
                                 + (((mw * 2 + (g & 1)) ^ r8) << 4));
    // B-trans: groups (k0,n0)(k8,n0)(k0,n8)(k8,n8)
    unsigned b_rbase = (unsigned)(((g & 1) * 8 + r8) * 256);
    int b_cxor = (nw * 8 + (g >> 1));   // + pn*2, then ^ r8

    #pragma unroll 1
    for (int t = 0; t < OG_TILES; t++) {
        __syncthreads();
        // commit C tile (hi/lo bf16, swizzled): float4 -> uint2 halves
        #pragma unroll
        for (int q = 0; q < 4; q++) {
            int row = sc_row + q * 8;
            float4 f = rc[q];
            float hx = __bfloat162float(__float2bfloat16(f.x));
            float hy = __bfloat162float(__float2bfloat16(f.y));
            float hz = __bfloat162float(__float2bfloat16(f.z));
            float hw = __bfloat162float(__float2bfloat16(f.w));
            uint2 hi = make_uint2(cvt2bf(f.x, f.y), cvt2bf(f.z, f.w));
            uint2 lo = make_uint2(cvt2bf(f.x - hx, f.y - hy), cvt2bf(f.z - hz, f.w - hw));
            unsigned off = (unsigned)(row * 256 + (((sc4 >> 1) ^ (row & 7)) << 4)
                                      + (sc4 & 1) * 8);
            *(uint2*)(osm + C_HI + off) = hi;
            *(uint2*)(osm + C_LO + off) = lo;
        }
        // commit w tile to [v][b] (hi/lo bf16 scalars, swizzled rows of 128B)
        #pragma unroll
        for (int q = 0; q < 2; q++) {
            int fi = tid + q * 256;
            int b_ = fi >> 3, v4 = fi & 7;
            float fv[4] = {rw[q].x, rw[q].y, rw[q].z, rw[q].w};
            #pragma unroll
            for (int j = 0; j < 4; j++) {
                int vr = v4 * 4 + j;
                __nv_bfloat16 h = __float2bfloat16(fv[j]);
                __nv_bfloat16 l = __float2bfloat16(fv[j] - __bfloat162float(h));
                unsigned off = (unsigned)(vr * 128 + (((b_ >> 3) ^ (vr & 7)) << 4)
                                          + (b_ & 7) * 2);
                *(__nv_bfloat16*)(osm + W_HI + off) = h;
                *(__nv_bfloat16*)(osm + W_LO + off) = l;
            }
        }
        __syncthreads();

        // prefetch next tile
        if (t + 1 < OG_TILES) {
            int vb = vstart + (t + 1) * 32;
            #pragma unroll
            for (int q = 0; q < 4; q++) {
                int v = vb + sc_row + q * 8;
                rc[q] = make_float4(0.f, 0.f, 0.f, 0.f);
                if (v < VV) rc[q] = *(const float4*)(Ct + (size_t)v * DD + sc4 * 4);
            }
            #pragma unroll
            for (int q = 0; q < 2; q++) {
                int fi = tid + q * 256;
                int b_ = fi >> 3, v4 = fi & 7;
                int v = vb + v4 * 4;
                rw[q] = make_float4(0.f, 0.f, 0.f, 0.f);
                if (v < VV) rw[q] = *(const float4*)(g_w + (size_t)b_ * VV + v);
            }
        }

        // MMA over 2 ksteps of 16 v
        #pragma unroll
        for (int ks = 0; ks < 2; ks++) {
            unsigned a_hi[4], a_lo[4];
            unsigned aoff = (unsigned)(ks * 16 * 128) + a_roff;
            ldsm_x4_t(a_hi, sbase + W_HI + aoff);
            ldsm_x4_t(a_lo, sbase + W_LO + aoff);
            #pragma unroll
            for (int pn = 0; pn < 4; pn++) {
                unsigned boff = (unsigned)(ks * 16 * 256) + b_rbase
                              + (unsigned)(((b_cxor + pn * 2) ^ r8) << 4);
                unsigned bh[4], bl[4];
                ldsm_x4_t(bh, sbase + C_HI + boff);
                ldsm_x4_t(bl, sbase + C_LO + boff);
                mma16816(acc[2 * pn],     a_hi, bh[0], bh[1]);
                mma16816(acc[2 * pn],     a_hi, bl[0], bl[1]);
                mma16816(acc[2 * pn],     a_lo, bh[0], bh[1]);
                mma16816(acc[2 * pn + 1], a_hi, bh[2], bh[3]);
                mma16816(acc[2 * pn + 1], a_hi, bl[2], bl[3]);
                mma16816(acc[2 * pn + 1], a_lo, bh[2], bh[3]);
            }
        }
    }

    // epilogue: D (m=b, n=d) -> atomicAdd into u
    int br0 = mw * 16 + (lane >> 2);
    int nq = (lane & 3) * 2;
    #pragma unroll
    for (int na = 0; na < 8; na++) {
        int d = nw * 64 + na * 8 + nq;
        atomicAdd(&u[br0 * DD + d],       acc[na][0]);
        atomicAdd(&u[br0 * DD + d + 1],   acc[na][1]);
        atomicAdd(&u[(br0 + 8) * DD + d],     acc[na][2]);
        atomicAdd(&u[(br0 + 8) * DD + d + 1], acc[na][3]);
    }

    // zero own w chunk for the next hop's scatter (chunks disjoint per block)
    if (do_zero) {
        float4 z = make_float4(0.f, 0.f, 0.f, 0.f);
        for (int idx = tid; idx < 64 * 48; idx += 256) {
            int b_ = idx / 48;
            int v = vstart + (idx % 48) * 4;
            if (v < VV)
                *(float4*)&g_w[(size_t)b_ * VV + v] = z;
        }
    }
}

// ---------------------------------------------------------------------------
extern "C" void kernel_launch(void* const* d_in, const int* in_sizes, int n_in,
                              void* d_out, int out_size) {
    int si = 0, ci = 1;
    if (n_in >= 2 && in_sizes[0] > in_sizes[1]) { si = 1; ci = 0; }
    const void* story = d_in[si];
    const float* C = (const float*)d_in[ci];
    float* u = (float*)d_out;

    const int PG_SMEM = 98304;   // A hi/lo 32K*2 + B hi/lo 16K*2
    static int smem_set = 0;
    if (!smem_set) {
        cudaFuncSetAttribute(p_gemm_mma, cudaFuncAttributeMaxDynamicSharedMemorySize, PG_SMEM);
        smem_set = 1;
    }

    prologue<<<3127, 256>>>((const unsigned int*)story, u);

    for (int h = 0; h < 3; h++) {
        if (h) p_gemm_mma<<<PG_GRID, 256, PG_SMEM>>>(C + (size_t)h * VV * DD, u);
        fused_attn<<<BB, 512>>>(story, h > 0 ? 1 : 0);
        o_gemm_mma<<<OG_GRID, 256>>>(C + (size_t)(h + 1) * VV * DD, u, h < 2 ? 1 : 0);
    }
}